// round 7
// baseline (speedup 1.0000x reference)
#include <cuda_runtime.h>
#include <math.h>

// DoMINO point-MLP, TWO (point,neighbor) items per thread (same point),
// weight loads shared between the two items; sin/cos features parked in
// dynamic shared memory (float2 pairs) to fit 4 CTAs/SM (128-reg cap).
// 33 -> 64 (gelu) -> 32 (gelu) -> 8 (tanh), masked sum over P=10,
// out (8,64,48,32) fp32, reduced via global RED into pre-zeroed d_out.

namespace {
constexpr int N_PTS = 98304;       // 64*48*32
constexpr int NB    = 10;
constexpr int NITEM = N_PTS * NB;  // 983040
constexpr int NTHRD = NITEM / 2;   // 491520 threads, 2 items each
// weight region layout (floats) at base of dynamic smem
constexpr int OFF_W1 = 0;      // 33*64 = 2112
constexpr int OFF_B1 = 2112;   // 64
constexpr int OFF_W2 = 2176;   // 64*32 = 2048
constexpr int OFF_B2 = 4224;   // 32
constexpr int OFF_W3 = 4256;   // 32*8 = 256
constexpr int OFF_B3 = 4512;   // 8
constexpr int OFF_FR = 4520;   // 5 (+3 pad)
constexpr int W_TOT  = 4528;   // floats (even -> 8B aligned end)
// feature region: per-thread 30 float2 slots, stride 31 (odd -> conflict-free)
constexpr int FEAT_STRIDE = 31;                    // float2 units per thread
constexpr int FEAT_F2     = 128 * FEAT_STRIDE;     // 3968 float2
constexpr size_t SMEM_BYTES = (size_t)W_TOT * 4 + (size_t)FEAT_F2 * 8; // 49856
}

typedef unsigned long long u64;

__device__ __forceinline__ u64 pk2(float x, float y) {
    u64 r;
    asm("mov.b64 %0, {%1, %2};" : "=l"(r) : "f"(x), "f"(y));
    return r;
}
__device__ __forceinline__ void up2(u64 a, float& x, float& y) {
    asm("mov.b64 {%0, %1}, %2;" : "=f"(x), "=f"(y) : "l"(a));
}
// packed dual fp32 FMA: d = a*b + d (exact fp32 on both halves)
__device__ __forceinline__ void fma2(u64& d, u64 a, u64 b) {
    asm("fma.rn.f32x2 %0, %1, %2, %0;" : "+l"(d) : "l"(a), "l"(b));
}

// GELU with Abramowitz-Stegun 7.1.26 erf (|err| <= 1.5e-7).
__device__ __forceinline__ float gelu_fast(float v) {
    const float z  = v * 0.70710678118654752440f;
    const float za = fabsf(z);
    float t;
    asm("rcp.approx.f32 %0, %1;" : "=f"(t) : "f"(fmaf(0.3275911f, za, 1.0f)));
    float poly = fmaf(1.061405429f, t, -1.453152027f);
    poly = fmaf(poly, t, 1.421413741f);
    poly = fmaf(poly, t, -0.284496736f);
    poly = fmaf(poly, t, 0.254829592f);
    poly *= t;
    const float e  = __expf(-za * za);
    float erfa = fmaf(-poly, e, 1.0f);          // erf(|z|)
    float erfz = copysignf(erfa, z);
    return 0.5f * v * (1.0f + erfz);
}
// fast tanh: (e^2x - 1)/(e^2x + 1), clamped so e never overflows.
__device__ __forceinline__ float fast_tanh(float v) {
    float c = fminf(fmaxf(v, -15.0f), 15.0f);
    float e = __expf(2.0f * c);
    return __fdividef(e - 1.0f, e + 1.0f);
}

__global__ void zero_out_kernel(float* __restrict__ out, int n4) {
    int i = blockIdx.x * blockDim.x + threadIdx.x;
    if (i < n4) reinterpret_cast<float4*>(out)[i] = make_float4(0.f, 0.f, 0.f, 0.f);
}

__global__ void __launch_bounds__(128, 4)
domino_kernel(const float* __restrict__ x,
              const float* __restrict__ freqs,
              const float* __restrict__ W1, const float* __restrict__ b1,
              const float* __restrict__ W2, const float* __restrict__ b2,
              const float* __restrict__ W3, const float* __restrict__ b3,
              float* __restrict__ out)
{
    extern __shared__ __align__(16) float sm[];
    float2* feat = reinterpret_cast<float2*>(sm + W_TOT) +
                   (size_t)threadIdx.x * FEAT_STRIDE;

    // stage weights/biases/freqs into shared (broadcast source for the block)
    for (int i = threadIdx.x; i < 2112; i += blockDim.x) sm[OFF_W1 + i] = W1[i];
    for (int i = threadIdx.x; i < 64;   i += blockDim.x) sm[OFF_B1 + i] = b1[i];
    for (int i = threadIdx.x; i < 2048; i += blockDim.x) sm[OFF_W2 + i] = W2[i];
    for (int i = threadIdx.x; i < 32;   i += blockDim.x) sm[OFF_B2 + i] = b2[i];
    for (int i = threadIdx.x; i < 256;  i += blockDim.x) sm[OFF_W3 + i] = W3[i];
    for (int i = threadIdx.x; i < 8;    i += blockDim.x) sm[OFF_B3 + i] = b3[i];
    for (int i = threadIdx.x; i < 8;    i += blockDim.x) sm[OFF_FR + i] = (i < 5) ? freqs[i] : 0.0f;
    __syncthreads();

    const int t = blockIdx.x * blockDim.x + threadIdx.x;   // grid exact
    const int n = t / 5;                                   // output point index

    // items 2t and 2t+1 (same point): 6 consecutive floats, 8B aligned
    const float2* xv = reinterpret_cast<const float2*>(x + (size_t)t * 6);
    const float2 v0 = xv[0], v1 = xv[1], v2 = xv[2];
    const float xa0 = v0.x, xa1 = v0.y, xa2 = v1.x;
    const float xb0 = v1.y, xb1 = v2.x, xb2 = v2.y;
    const float ma = (fabsf(xa0) > 1e-6f) ? 1.0f : 0.0f;   // padded-neighbor masks
    const float mb = (fabsf(xb0) > 1e-6f) ? 1.0f : 0.0f;

    // double2 = 4 floats. Row sizes in double2: W1 row(64f)=16, W2 row(32f)=8, W3 row(8f)=2.
    const double2* W1v = reinterpret_cast<const double2*>(sm + OFF_W1);
    const u64*     b1v = reinterpret_cast<const u64*>(sm + OFF_B1);
    const double2* W2v = reinterpret_cast<const double2*>(sm + OFF_W2);
    const u64*     b2v = reinterpret_cast<const u64*>(sm + OFF_B2);
    const double2* W3v = reinterpret_cast<const double2*>(sm + OFF_W3);
    const u64*     b3v = reinterpret_cast<const u64*>(sm + OFF_B3);

    // ---- sin/cos features for both items -> smem float2 {item_a, item_b} ----
    // slot j in [0,15): sin(m*3+d);  slot 15+j: cos.  (f[3+j] / f[18+j])
    {
        const float ca[3] = {xa0, xa1, xa2};
        const float cb[3] = {xb0, xb1, xb2};
#pragma unroll
        for (int m = 0; m < 5; m++) {
            const float frm = sm[OFF_FR + m];
#pragma unroll
            for (int d = 0; d < 3; d++) {
                float sa, caa, sb, cbb;
                __sincosf(ca[d] * frm, &sa, &caa);
                __sincosf(cb[d] * frm, &sb, &cbb);
                feat[m * 3 + d]      = make_float2(sa, sb);
                feat[15 + m * 3 + d] = make_float2(caa, cbb);
            }
        }
    }
    // no sync needed: each thread reads only its own feature slots

    // ---- layer 2 accumulators (32 outputs = 16 packed) per item ----
    u64 a2a[16], a2b[16];
#pragma unroll
    for (int kp = 0; kp < 16; kp++) { a2a[kp] = b2v[kp]; a2b[kp] = a2a[kp]; }

    // ---- layer 1 in 4 chunks of 16 outputs, streamed into layer 2 ----
#pragma unroll 1
    for (int jc = 0; jc < 4; jc++) {
        u64 c1a[8], c1b[8];
#pragma unroll
        for (int q = 0; q < 8; q++) { c1a[q] = b1v[jc * 8 + q]; c1b[q] = c1a[q]; }

#pragma unroll
        for (int i = 0; i < 33; i++) {
            float fva, fvb;
            if (i == 0)      { fva = xa0; fvb = xb0; }
            else if (i == 1) { fva = xa1; fvb = xb1; }
            else if (i == 2) { fva = xa2; fvb = xb2; }
            else             { const float2 p = feat[i - 3]; fva = p.x; fvb = p.y; }
            const u64 ffa = pk2(fva, fva);
            const u64 ffb = pk2(fvb, fvb);
            const double2* wrow = W1v + i * 16 + jc * 4;
#pragma unroll
            for (int q = 0; q < 4; q++) {
                const double2 w = wrow[q];           // one LDS.128, serves both items
                const u64 wx = __double_as_longlong(w.x);
                const u64 wy = __double_as_longlong(w.y);
                fma2(c1a[2 * q],     ffa, wx);
                fma2(c1a[2 * q + 1], ffa, wy);
                fma2(c1b[2 * q],     ffb, wx);
                fma2(c1b[2 * q + 1], ffb, wy);
            }
        }

        // gelu the 16 chunk outputs of each item; stream into layer 2
#pragma unroll
        for (int q = 0; q < 8; q++) {
            float ua, va, ub, vb;
            up2(c1a[q], ua, va);
            up2(c1b[q], ub, vb);
            const float gau = gelu_fast(ua), gav = gelu_fast(va);
            const float gbu = gelu_fast(ub), gbv = gelu_fast(vb);
            const u64 hau = pk2(gau, gau);
            const u64 hav = pk2(gav, gav);
            const u64 hbu = pk2(gbu, gbu);
            const u64 hbv = pk2(gbv, gbv);
            const int j0 = jc * 16 + 2 * q;
            const double2* w2a = W2v + (size_t)j0 * 8;   // row j0 (8 double2 = 32 floats)
            const double2* w2b = w2a + 8;                // row j0+1
#pragma unroll
            for (int kq = 0; kq < 8; kq++) {
                const double2 wa = w2a[kq];              // one LDS.128 serves both items
                const u64 wax = __double_as_longlong(wa.x);
                const u64 way = __double_as_longlong(wa.y);
                fma2(a2a[2 * kq],     hau, wax);
                fma2(a2a[2 * kq + 1], hau, way);
                fma2(a2b[2 * kq],     hbu, wax);
                fma2(a2b[2 * kq + 1], hbu, way);
                const double2 wb = w2b[kq];
                const u64 wbx = __double_as_longlong(wb.x);
                const u64 wby = __double_as_longlong(wb.y);
                fma2(a2a[2 * kq],     hav, wbx);
                fma2(a2a[2 * kq + 1], hav, wby);
                fma2(a2b[2 * kq],     hbv, wbx);
                fma2(a2b[2 * kq + 1], hbv, wby);
            }
        }
    }

    // ---- layer 3: consume a2 pairwise; h2 never materialized ----
    u64 a3a[4], a3b[4];
#pragma unroll
    for (int cp = 0; cp < 4; cp++) { a3a[cp] = b3v[cp]; a3b[cp] = a3a[cp]; }
#pragma unroll
    for (int q = 0; q < 16; q++) {
        float ua, va, ub, vb;
        up2(a2a[q], ua, va);
        up2(a2b[q], ub, vb);
        const float gau = gelu_fast(ua), gav = gelu_fast(va);
        const float gbu = gelu_fast(ub), gbv = gelu_fast(vb);
        const u64 hau = pk2(gau, gau);
        const u64 hav = pk2(gav, gav);
        const u64 hbu = pk2(gbu, gbu);
        const u64 hbv = pk2(gbv, gbv);
        const int k0 = 2 * q;
        const double2* w3a = W3v + (size_t)k0 * 2;   // row k0 (2 double2 = 8 floats)
        const double2* w3b = w3a + 2;                // row k0+1
#pragma unroll
        for (int cq = 0; cq < 2; cq++) {
            const double2 wa = w3a[cq];
            const double2 wb = w3b[cq];
            const u64 wax = __double_as_longlong(wa.x);
            const u64 way = __double_as_longlong(wa.y);
            const u64 wbx = __double_as_longlong(wb.x);
            const u64 wby = __double_as_longlong(wb.y);
            fma2(a3a[2 * cq],     hau, wax);
            fma2(a3a[2 * cq + 1], hau, way);
            fma2(a3a[2 * cq],     hav, wbx);
            fma2(a3a[2 * cq + 1], hav, wby);
            fma2(a3b[2 * cq],     hbu, wax);
            fma2(a3b[2 * cq + 1], hbu, way);
            fma2(a3b[2 * cq],     hbv, wbx);
            fma2(a3b[2 * cq + 1], hbv, wby);
        }
    }

    // ---- tanh, mask, combine the two items, reduce via global RED ----
#pragma unroll
    for (int cp = 0; cp < 4; cp++) {
        float ua, va, ub, vb;
        up2(a3a[cp], ua, va);
        up2(a3b[cp], ub, vb);
        const float r0 = ma * fast_tanh(ua) + mb * fast_tanh(ub);
        const float r1 = ma * fast_tanh(va) + mb * fast_tanh(vb);
        atomicAdd(&out[(size_t)(2 * cp)     * N_PTS + n], r0);
        atomicAdd(&out[(size_t)(2 * cp + 1) * N_PTS + n], r1);
    }
}

extern "C" void kernel_launch(void* const* d_in, const int* in_sizes, int n_in,
                              void* d_out, int out_size)
{
    (void)in_sizes; (void)n_in; (void)out_size;
    const float* x     = (const float*)d_in[0];
    // d_in[1] = grid : unused by the reference math
    const float* freqs = (const float*)d_in[2];
    const float* W1    = (const float*)d_in[3];
    const float* b1    = (const float*)d_in[4];
    const float* W2    = (const float*)d_in[5];
    const float* b2    = (const float*)d_in[6];
    const float* W3    = (const float*)d_in[7];
    const float* b3    = (const float*)d_in[8];
    float* out = (float*)d_out;

    // opt-in for >48KB dynamic smem (host-side, capture-safe, idempotent)
    static bool attr_set = false;
    if (!attr_set) {
        cudaFuncSetAttribute(domino_kernel,
                             cudaFuncAttributeMaxDynamicSharedMemorySize,
                             (int)SMEM_BYTES);
        attr_set = true;
    }

    // zero the output (8 * N_PTS floats = 786432 -> 196608 float4)
    const int n4 = (8 * N_PTS) / 4;
    zero_out_kernel<<<(n4 + 255) / 256, 256>>>(out, n4);

    domino_kernel<<<NTHRD / 128, 128, SMEM_BYTES>>>(x, freqs, W1, b1, W2, b2,
                                                    W3, b3, out);
}

// round 8
// speedup vs baseline: 1.0436x; 1.0436x over previous
#include <cuda_runtime.h>
#include <math.h>

// DoMINO point-MLP, TWO (point,neighbor) items per thread (same point),
// weight loads shared between the two items. Fourier features are RECOMPUTED
// per layer-1 chunk (MUFU is cheap) so no f[33] arrays stay live -> fits
// 4 CTAs/SM at <=128 regs without spilling.
// 33 -> 64 (gelu) -> 32 (gelu) -> 8 (tanh), masked sum over P=10,
// out (8,64,48,32) fp32, reduced via global RED into pre-zeroed d_out.

namespace {
constexpr int N_PTS = 98304;       // 64*48*32
constexpr int NB    = 10;
constexpr int NITEM = N_PTS * NB;  // 983040
constexpr int NTHRD = NITEM / 2;   // 491520 threads, 2 items each
// shared layout (floats); all offsets even -> 8B/16B aligned views OK
constexpr int OFF_W1 = 0;      // 33*64 = 2112
constexpr int OFF_B1 = 2112;   // 64
constexpr int OFF_W2 = 2176;   // 64*32 = 2048
constexpr int OFF_B2 = 4224;   // 32
constexpr int OFF_W3 = 4256;   // 32*8 = 256
constexpr int OFF_B3 = 4512;   // 8
constexpr int OFF_FR = 4520;   // 5 (+3 pad)
constexpr int SM_TOT = 4528;
}

typedef unsigned long long u64;

__device__ __forceinline__ u64 pk2(float x, float y) {
    u64 r;
    asm("mov.b64 %0, {%1, %2};" : "=l"(r) : "f"(x), "f"(y));
    return r;
}
__device__ __forceinline__ void up2(u64 a, float& x, float& y) {
    asm("mov.b64 {%0, %1}, %2;" : "=f"(x), "=f"(y) : "l"(a));
}
// packed dual fp32 FMA: d = a*b + d (exact fp32 on both halves)
__device__ __forceinline__ void fma2(u64& d, u64 a, u64 b) {
    asm("fma.rn.f32x2 %0, %1, %2, %0;" : "+l"(d) : "l"(a), "l"(b));
}

// GELU with Abramowitz-Stegun 7.1.26 erf (|err| <= 1.5e-7).
__device__ __forceinline__ float gelu_fast(float v) {
    const float z  = v * 0.70710678118654752440f;
    const float za = fabsf(z);
    float t;
    asm("rcp.approx.f32 %0, %1;" : "=f"(t) : "f"(fmaf(0.3275911f, za, 1.0f)));
    float poly = fmaf(1.061405429f, t, -1.453152027f);
    poly = fmaf(poly, t, 1.421413741f);
    poly = fmaf(poly, t, -0.284496736f);
    poly = fmaf(poly, t, 0.254829592f);
    poly *= t;
    const float e  = __expf(-za * za);
    float erfa = fmaf(-poly, e, 1.0f);          // erf(|z|)
    float erfz = copysignf(erfa, z);
    return 0.5f * v * (1.0f + erfz);
}
// fast tanh: (e^2x - 1)/(e^2x + 1), clamped so e never overflows.
__device__ __forceinline__ float fast_tanh(float v) {
    float c = fminf(fmaxf(v, -15.0f), 15.0f);
    float e = __expf(2.0f * c);
    return __fdividef(e - 1.0f, e + 1.0f);
}

__global__ void zero_out_kernel(float* __restrict__ out, int n4) {
    int i = blockIdx.x * blockDim.x + threadIdx.x;
    if (i < n4) reinterpret_cast<float4*>(out)[i] = make_float4(0.f, 0.f, 0.f, 0.f);
}

__global__ void __launch_bounds__(128, 4)
domino_kernel(const float* __restrict__ x,
              const float* __restrict__ freqs,
              const float* __restrict__ W1, const float* __restrict__ b1,
              const float* __restrict__ W2, const float* __restrict__ b2,
              const float* __restrict__ W3, const float* __restrict__ b3,
              float* __restrict__ out)
{
    __shared__ __align__(16) float sm[SM_TOT];

    // stage weights/biases/freqs into shared (broadcast source for the block)
    for (int i = threadIdx.x; i < 2112; i += blockDim.x) sm[OFF_W1 + i] = W1[i];
    for (int i = threadIdx.x; i < 64;   i += blockDim.x) sm[OFF_B1 + i] = b1[i];
    for (int i = threadIdx.x; i < 2048; i += blockDim.x) sm[OFF_W2 + i] = W2[i];
    for (int i = threadIdx.x; i < 32;   i += blockDim.x) sm[OFF_B2 + i] = b2[i];
    for (int i = threadIdx.x; i < 256;  i += blockDim.x) sm[OFF_W3 + i] = W3[i];
    for (int i = threadIdx.x; i < 8;    i += blockDim.x) sm[OFF_B3 + i] = b3[i];
    for (int i = threadIdx.x; i < 8;    i += blockDim.x) sm[OFF_FR + i] = (i < 5) ? freqs[i] : 0.0f;
    __syncthreads();

    const int t = blockIdx.x * blockDim.x + threadIdx.x;   // grid exact
    const int n = t / 5;                                   // output point index

    // items 2t and 2t+1 (same point): 6 consecutive floats, 8B aligned
    const float2* xv = reinterpret_cast<const float2*>(x + (size_t)t * 6);
    const float2 v0 = xv[0], v1 = xv[1], v2 = xv[2];
    const float xa0 = v0.x, xa1 = v0.y, xa2 = v1.x;
    const float xb0 = v1.y, xb1 = v2.x, xb2 = v2.y;
    const float ma = (fabsf(xa0) > 1e-6f) ? 1.0f : 0.0f;   // padded-neighbor masks
    const float mb = (fabsf(xb0) > 1e-6f) ? 1.0f : 0.0f;

    // double2 = 4 floats. Row sizes in double2: W1 row(64f)=16, W2 row(32f)=8, W3 row(8f)=2.
    const double2* W1v = reinterpret_cast<const double2*>(sm + OFF_W1);
    const u64*     b1v = reinterpret_cast<const u64*>(sm + OFF_B1);
    const double2* W2v = reinterpret_cast<const double2*>(sm + OFF_W2);
    const u64*     b2v = reinterpret_cast<const u64*>(sm + OFF_B2);
    const double2* W3v = reinterpret_cast<const double2*>(sm + OFF_W3);
    const u64*     b3v = reinterpret_cast<const u64*>(sm + OFF_B3);

    // ---- layer 2 accumulators (32 outputs = 16 packed) per item ----
    u64 a2a[16], a2b[16];
#pragma unroll
    for (int kp = 0; kp < 16; kp++) { a2a[kp] = b2v[kp]; a2b[kp] = a2a[kp]; }

    // ---- layer 1 in 4 chunks of 16 outputs, streamed into layer 2;
    //      Fourier features recomputed per chunk (no f[] arrays live) ----
#pragma unroll 1
    for (int jc = 0; jc < 4; jc++) {
        u64 c1a[8], c1b[8];
#pragma unroll
        for (int q = 0; q < 8; q++) { c1a[q] = b1v[jc * 8 + q]; c1b[q] = c1a[q]; }

        // one layer-1 input row for both items: 4 LDS.128 + 16 fma2
        auto l1row = [&](int i, float fva, float fvb) {
            const u64 ffa = pk2(fva, fva);
            const u64 ffb = pk2(fvb, fvb);
            const double2* wrow = W1v + i * 16 + jc * 4;
#pragma unroll
            for (int q = 0; q < 4; q++) {
                const double2 w = wrow[q];           // one LDS.128, serves both items
                const u64 wx = __double_as_longlong(w.x);
                const u64 wy = __double_as_longlong(w.y);
                fma2(c1a[2 * q],     ffa, wx);
                fma2(c1a[2 * q + 1], ffa, wy);
                fma2(c1b[2 * q],     ffb, wx);
                fma2(c1b[2 * q + 1], ffb, wy);
            }
        };

        l1row(0, xa0, xb0);
        l1row(1, xa1, xb1);
        l1row(2, xa2, xb2);
        {
            const float ca[3] = {xa0, xa1, xa2};
            const float cb[3] = {xb0, xb1, xb2};
#pragma unroll
            for (int m = 0; m < 5; m++) {
                const float frm = sm[OFF_FR + m];    // LDS broadcast
#pragma unroll
                for (int d = 0; d < 3; d++) {
                    float sa, caa, sb, cbb;
                    __sincosf(ca[d] * frm, &sa, &caa);
                    __sincosf(cb[d] * frm, &sb, &cbb);
                    l1row(3  + m * 3 + d, sa, sb);
                    l1row(18 + m * 3 + d, caa, cbb);
                }
            }
        }

        // gelu the 16 chunk outputs of each item; stream into layer 2
#pragma unroll
        for (int q = 0; q < 8; q++) {
            float ua, va, ub, vb;
            up2(c1a[q], ua, va);
            up2(c1b[q], ub, vb);
            const float gau = gelu_fast(ua), gav = gelu_fast(va);
            const float gbu = gelu_fast(ub), gbv = gelu_fast(vb);
            const u64 hau = pk2(gau, gau);
            const u64 hav = pk2(gav, gav);
            const u64 hbu = pk2(gbu, gbu);
            const u64 hbv = pk2(gbv, gbv);
            const int j0 = jc * 16 + 2 * q;
            const double2* w2a = W2v + (size_t)j0 * 8;   // row j0 (8 double2 = 32 floats)
            const double2* w2b = w2a + 8;                // row j0+1
#pragma unroll
            for (int kq = 0; kq < 8; kq++) {
                const double2 wa = w2a[kq];              // one LDS.128 serves both items
                const u64 wax = __double_as_longlong(wa.x);
                const u64 way = __double_as_longlong(wa.y);
                fma2(a2a[2 * kq],     hau, wax);
                fma2(a2a[2 * kq + 1], hau, way);
                fma2(a2b[2 * kq],     hbu, wax);
                fma2(a2b[2 * kq + 1], hbu, way);
                const double2 wb = w2b[kq];
                const u64 wbx = __double_as_longlong(wb.x);
                const u64 wby = __double_as_longlong(wb.y);
                fma2(a2a[2 * kq],     hav, wbx);
                fma2(a2a[2 * kq + 1], hav, wby);
                fma2(a2b[2 * kq],     hbv, wbx);
                fma2(a2b[2 * kq + 1], hbv, wby);
            }
        }
    }

    // ---- layer 3: consume a2 pairwise; h2 never materialized ----
    u64 a3a[4], a3b[4];
#pragma unroll
    for (int cp = 0; cp < 4; cp++) { a3a[cp] = b3v[cp]; a3b[cp] = a3a[cp]; }
#pragma unroll
    for (int q = 0; q < 16; q++) {
        float ua, va, ub, vb;
        up2(a2a[q], ua, va);
        up2(a2b[q], ub, vb);
        const float gau = gelu_fast(ua), gav = gelu_fast(va);
        const float gbu = gelu_fast(ub), gbv = gelu_fast(vb);
        const u64 hau = pk2(gau, gau);
        const u64 hav = pk2(gav, gav);
        const u64 hbu = pk2(gbu, gbu);
        const u64 hbv = pk2(gbv, gbv);
        const int k0 = 2 * q;
        const double2* w3a = W3v + (size_t)k0 * 2;   // row k0 (2 double2 = 8 floats)
        const double2* w3b = w3a + 2;                // row k0+1
#pragma unroll
        for (int cq = 0; cq < 2; cq++) {
            const double2 wa = w3a[cq];
            const double2 wb = w3b[cq];
            const u64 wax = __double_as_longlong(wa.x);
            const u64 way = __double_as_longlong(wa.y);
            const u64 wbx = __double_as_longlong(wb.x);
            const u64 wby = __double_as_longlong(wb.y);
            fma2(a3a[2 * cq],     hau, wax);
            fma2(a3a[2 * cq + 1], hau, way);
            fma2(a3a[2 * cq],     hav, wbx);
            fma2(a3a[2 * cq + 1], hav, wby);
            fma2(a3b[2 * cq],     hbu, wax);
            fma2(a3b[2 * cq + 1], hbu, way);
            fma2(a3b[2 * cq],     hbv, wbx);
            fma2(a3b[2 * cq + 1], hbv, wby);
        }
    }

    // ---- tanh, mask, combine the two items, reduce via global RED ----
#pragma unroll
    for (int cp = 0; cp < 4; cp++) {
        float ua, va, ub, vb;
        up2(a3a[cp], ua, va);
        up2(a3b[cp], ub, vb);
        const float r0 = ma * fast_tanh(ua) + mb * fast_tanh(ub);
        const float r1 = ma * fast_tanh(va) + mb * fast_tanh(vb);
        atomicAdd(&out[(size_t)(2 * cp)     * N_PTS + n], r0);
        atomicAdd(&out[(size_t)(2 * cp + 1) * N_PTS + n], r1);
    }
}

extern "C" void kernel_launch(void* const* d_in, const int* in_sizes, int n_in,
                              void* d_out, int out_size)
{
    (void)in_sizes; (void)n_in; (void)out_size;
    const float* x     = (const float*)d_in[0];
    // d_in[1] = grid : unused by the reference math
    const float* freqs = (const float*)d_in[2];
    const float* W1    = (const float*)d_in[3];
    const float* b1    = (const float*)d_in[4];
    const float* W2    = (const float*)d_in[5];
    const float* b2    = (const float*)d_in[6];
    const float* W3    = (const float*)d_in[7];
    const float* b3    = (const float*)d_in[8];
    float* out = (float*)d_out;

    // zero the output (8 * N_PTS floats = 786432 -> 196608 float4)
    const int n4 = (8 * N_PTS) / 4;
    zero_out_kernel<<<(n4 + 255) / 256, 256>>>(out, n4);

    domino_kernel<<<NTHRD / 128, 128>>>(x, freqs, W1, b1, W2, b2, W3, b3, out);
}

// round 9
// speedup vs baseline: 1.1673x; 1.1185x over previous
#include <cuda_runtime.h>
#include <math.h>

// DoMINO point-MLP, TWO (point,neighbor) items per thread (same point).
// Weight LDS shared between items; Fourier features computed once into
// conflict-free smem (float2, stride 31); layer 1 in chunks of 8 outputs
// so live registers fit 4 CTAs/SM at 128 regs WITHOUT spilling.
// 33 -> 64 (gelu) -> 32 (gelu) -> 8 (tanh), masked sum over P=10,
// out (8,64,48,32) fp32, reduced via global RED into pre-zeroed d_out.

namespace {
constexpr int N_PTS = 98304;       // 64*48*32
constexpr int NB    = 10;
constexpr int NITEM = N_PTS * NB;  // 983040
constexpr int NTHRD = NITEM / 2;   // 491520 threads, 2 items each
// weight region layout (floats) at base of dynamic smem
constexpr int OFF_W1 = 0;      // 33*64 = 2112
constexpr int OFF_B1 = 2112;   // 64
constexpr int OFF_W2 = 2176;   // 64*32 = 2048
constexpr int OFF_B2 = 4224;   // 32
constexpr int OFF_W3 = 4256;   // 32*8 = 256
constexpr int OFF_B3 = 4512;   // 8
constexpr int OFF_FR = 4520;   // 5 (+3 pad)
constexpr int W_TOT  = 4528;   // floats (even -> 8B aligned end)
// feature region: 30 float2 slots per thread, stride 31 (conflict-free for
// LDS.64: lane diff d in a half-warp gives word offset 30d mod 32 != 0)
constexpr int FEAT_STRIDE = 31;                    // float2 units per thread
constexpr int FEAT_F2     = 128 * FEAT_STRIDE;     // 3968 float2
constexpr size_t SMEM_BYTES = (size_t)W_TOT * 4 + (size_t)FEAT_F2 * 8; // 49856
}

typedef unsigned long long u64;

__device__ __forceinline__ u64 pk2(float x, float y) {
    u64 r;
    asm("mov.b64 %0, {%1, %2};" : "=l"(r) : "f"(x), "f"(y));
    return r;
}
__device__ __forceinline__ void up2(u64 a, float& x, float& y) {
    asm("mov.b64 {%0, %1}, %2;" : "=f"(x), "=f"(y) : "l"(a));
}
// packed dual fp32 FMA: d = a*b + d (exact fp32 on both halves)
__device__ __forceinline__ void fma2(u64& d, u64 a, u64 b) {
    asm("fma.rn.f32x2 %0, %1, %2, %0;" : "+l"(d) : "l"(a), "l"(b));
}

// GELU with Abramowitz-Stegun 7.1.26 erf (|err| <= 1.5e-7).
__device__ __forceinline__ float gelu_fast(float v) {
    const float z  = v * 0.70710678118654752440f;
    const float za = fabsf(z);
    float t;
    asm("rcp.approx.f32 %0, %1;" : "=f"(t) : "f"(fmaf(0.3275911f, za, 1.0f)));
    float poly = fmaf(1.061405429f, t, -1.453152027f);
    poly = fmaf(poly, t, 1.421413741f);
    poly = fmaf(poly, t, -0.284496736f);
    poly = fmaf(poly, t, 0.254829592f);
    poly *= t;
    const float e  = __expf(-za * za);
    float erfa = fmaf(-poly, e, 1.0f);          // erf(|z|)
    float erfz = copysignf(erfa, z);
    return 0.5f * v * (1.0f + erfz);
}
// fast tanh: (e^2x - 1)/(e^2x + 1), clamped so e never overflows.
__device__ __forceinline__ float fast_tanh(float v) {
    float c = fminf(fmaxf(v, -15.0f), 15.0f);
    float e = __expf(2.0f * c);
    return __fdividef(e - 1.0f, e + 1.0f);
}

__global__ void zero_out_kernel(float* __restrict__ out, int n4) {
    int i = blockIdx.x * blockDim.x + threadIdx.x;
    if (i < n4) reinterpret_cast<float4*>(out)[i] = make_float4(0.f, 0.f, 0.f, 0.f);
}

__global__ void __launch_bounds__(128, 4)
domino_kernel(const float* __restrict__ x,
              const float* __restrict__ freqs,
              const float* __restrict__ W1, const float* __restrict__ b1,
              const float* __restrict__ W2, const float* __restrict__ b2,
              const float* __restrict__ W3, const float* __restrict__ b3,
              float* __restrict__ out)
{
    extern __shared__ __align__(16) float sm[];
    float2* feat = reinterpret_cast<float2*>(sm + W_TOT) +
                   (size_t)threadIdx.x * FEAT_STRIDE;

    // stage weights/biases/freqs into shared (broadcast source for the block)
    for (int i = threadIdx.x; i < 2112; i += blockDim.x) sm[OFF_W1 + i] = W1[i];
    for (int i = threadIdx.x; i < 64;   i += blockDim.x) sm[OFF_B1 + i] = b1[i];
    for (int i = threadIdx.x; i < 2048; i += blockDim.x) sm[OFF_W2 + i] = W2[i];
    for (int i = threadIdx.x; i < 32;   i += blockDim.x) sm[OFF_B2 + i] = b2[i];
    for (int i = threadIdx.x; i < 256;  i += blockDim.x) sm[OFF_W3 + i] = W3[i];
    for (int i = threadIdx.x; i < 8;    i += blockDim.x) sm[OFF_B3 + i] = b3[i];
    for (int i = threadIdx.x; i < 8;    i += blockDim.x) sm[OFF_FR + i] = (i < 5) ? freqs[i] : 0.0f;
    __syncthreads();

    const int t = blockIdx.x * blockDim.x + threadIdx.x;   // grid exact
    const int n = t / 5;                                   // output point index

    // items 2t and 2t+1 (same point): 6 consecutive floats, 8B aligned
    const float2* xv = reinterpret_cast<const float2*>(x + (size_t)t * 6);
    const float2 v0 = xv[0], v1 = xv[1], v2 = xv[2];
    const float xa0 = v0.x, xa1 = v0.y, xa2 = v1.x;
    const float xb0 = v1.y, xb1 = v2.x, xb2 = v2.y;
    const float ma = (fabsf(xa0) > 1e-6f) ? 1.0f : 0.0f;   // padded-neighbor masks
    const float mb = (fabsf(xb0) > 1e-6f) ? 1.0f : 0.0f;

    // double2 = 4 floats. Row sizes in double2: W1 row(64f)=16, W2 row(32f)=8, W3 row(8f)=2.
    const double2* W1v = reinterpret_cast<const double2*>(sm + OFF_W1);
    const u64*     b1v = reinterpret_cast<const u64*>(sm + OFF_B1);
    const double2* W2v = reinterpret_cast<const double2*>(sm + OFF_W2);
    const u64*     b2v = reinterpret_cast<const u64*>(sm + OFF_B2);
    const double2* W3v = reinterpret_cast<const double2*>(sm + OFF_W3);
    const u64*     b3v = reinterpret_cast<const u64*>(sm + OFF_B3);

    // ---- sin/cos features for both items -> smem float2 {item_a, item_b} ----
    // slot j in [0,15): sin of input row 3+j;  slot 15+j: cos (row 18+j).
    {
        const float ca[3] = {xa0, xa1, xa2};
        const float cb[3] = {xb0, xb1, xb2};
#pragma unroll
        for (int m = 0; m < 5; m++) {
            const float frm = sm[OFF_FR + m];
#pragma unroll
            for (int d = 0; d < 3; d++) {
                float sa, caa, sb, cbb;
                __sincosf(ca[d] * frm, &sa, &caa);
                __sincosf(cb[d] * frm, &sb, &cbb);
                feat[m * 3 + d]      = make_float2(sa, sb);
                feat[15 + m * 3 + d] = make_float2(caa, cbb);
            }
        }
    }
    // no sync needed: each thread reads only its own feature slots

    // ---- layer 2 accumulators (32 outputs = 16 packed) per item ----
    u64 a2a[16], a2b[16];
#pragma unroll
    for (int kp = 0; kp < 16; kp++) { a2a[kp] = b2v[kp]; a2b[kp] = a2a[kp]; }

    // ---- layer 1 in 8 chunks of 8 outputs, streamed into layer 2 ----
#pragma unroll 1
    for (int jc = 0; jc < 8; jc++) {
        u64 c1a[4], c1b[4];
#pragma unroll
        for (int q = 0; q < 4; q++) { c1a[q] = b1v[jc * 4 + q]; c1b[q] = c1a[q]; }

#pragma unroll
        for (int i = 0; i < 33; i++) {
            float fva, fvb;
            if (i == 0)      { fva = xa0; fvb = xb0; }
            else if (i == 1) { fva = xa1; fvb = xb1; }
            else if (i == 2) { fva = xa2; fvb = xb2; }
            else             { const float2 p = feat[i - 3]; fva = p.x; fvb = p.y; }
            const u64 ffa = pk2(fva, fva);
            const u64 ffb = pk2(fvb, fvb);
            const double2* wrow = W1v + i * 16 + jc * 2;
#pragma unroll
            for (int q = 0; q < 2; q++) {
                const double2 w = wrow[q];           // one LDS.128, serves both items
                const u64 wx = __double_as_longlong(w.x);
                const u64 wy = __double_as_longlong(w.y);
                fma2(c1a[2 * q],     ffa, wx);
                fma2(c1a[2 * q + 1], ffa, wy);
                fma2(c1b[2 * q],     ffb, wx);
                fma2(c1b[2 * q + 1], ffb, wy);
            }
        }

        // gelu the 8 chunk outputs of each item; stream into layer 2
#pragma unroll
        for (int q = 0; q < 4; q++) {
            float ua, va, ub, vb;
            up2(c1a[q], ua, va);
            up2(c1b[q], ub, vb);
            const float gau = gelu_fast(ua), gav = gelu_fast(va);
            const float gbu = gelu_fast(ub), gbv = gelu_fast(vb);
            const u64 hau = pk2(gau, gau);
            const u64 hav = pk2(gav, gav);
            const u64 hbu = pk2(gbu, gbu);
            const u64 hbv = pk2(gbv, gbv);
            const int j0 = jc * 8 + 2 * q;
            const double2* w2a = W2v + (size_t)j0 * 8;   // row j0 (8 double2 = 32 floats)
            const double2* w2b = w2a + 8;                // row j0+1
#pragma unroll
            for (int kq = 0; kq < 8; kq++) {
                const double2 wa = w2a[kq];              // one LDS.128 serves both items
                const u64 wax = __double_as_longlong(wa.x);
                const u64 way = __double_as_longlong(wa.y);
                fma2(a2a[2 * kq],     hau, wax);
                fma2(a2a[2 * kq + 1], hau, way);
                fma2(a2b[2 * kq],     hbu, wax);
                fma2(a2b[2 * kq + 1], hbu, way);
                const double2 wb = w2b[kq];
                const u64 wbx = __double_as_longlong(wb.x);
                const u64 wby = __double_as_longlong(wb.y);
                fma2(a2a[2 * kq],     hav, wbx);
                fma2(a2a[2 * kq + 1], hav, wby);
                fma2(a2b[2 * kq],     hbv, wbx);
                fma2(a2b[2 * kq + 1], hbv, wby);
            }
        }
    }

    // ---- layer 3: consume a2 pairwise; h2 never materialized ----
    u64 a3a[4], a3b[4];
#pragma unroll
    for (int cp = 0; cp < 4; cp++) { a3a[cp] = b3v[cp]; a3b[cp] = a3a[cp]; }
#pragma unroll
    for (int q = 0; q < 16; q++) {
        float ua, va, ub, vb;
        up2(a2a[q], ua, va);
        up2(a2b[q], ub, vb);
        const float gau = gelu_fast(ua), gav = gelu_fast(va);
        const float gbu = gelu_fast(ub), gbv = gelu_fast(vb);
        const u64 hau = pk2(gau, gau);
        const u64 hav = pk2(gav, gav);
        const u64 hbu = pk2(gbu, gbu);
        const u64 hbv = pk2(gbv, gbv);
        const int k0 = 2 * q;
        const double2* w3a = W3v + (size_t)k0 * 2;   // row k0 (2 double2 = 8 floats)
        const double2* w3b = w3a + 2;                // row k0+1
#pragma unroll
        for (int cq = 0; cq < 2; cq++) {
            const double2 wa = w3a[cq];
            const double2 wb = w3b[cq];
            const u64 wax = __double_as_longlong(wa.x);
            const u64 way = __double_as_longlong(wa.y);
            const u64 wbx = __double_as_longlong(wb.x);
            const u64 wby = __double_as_longlong(wb.y);
            fma2(a3a[2 * cq],     hau, wax);
            fma2(a3a[2 * cq + 1], hau, way);
            fma2(a3a[2 * cq],     hav, wbx);
            fma2(a3a[2 * cq + 1], hav, wby);
            fma2(a3b[2 * cq],     hbu, wax);
            fma2(a3b[2 * cq + 1], hbu, way);
            fma2(a3b[2 * cq],     hbv, wbx);
            fma2(a3b[2 * cq + 1], hbv, wby);
        }
    }

    // ---- tanh, mask, combine the two items, reduce via global RED ----
#pragma unroll
    for (int cp = 0; cp < 4; cp++) {
        float ua, va, ub, vb;
        up2(a3a[cp], ua, va);
        up2(a3b[cp], ub, vb);
        const float r0 = ma * fast_tanh(ua) + mb * fast_tanh(ub);
        const float r1 = ma * fast_tanh(va) + mb * fast_tanh(vb);
        atomicAdd(&out[(size_t)(2 * cp)     * N_PTS + n], r0);
        atomicAdd(&out[(size_t)(2 * cp + 1) * N_PTS + n], r1);
    }
}

extern "C" void kernel_launch(void* const* d_in, const int* in_sizes, int n_in,
                              void* d_out, int out_size)
{
    (void)in_sizes; (void)n_in; (void)out_size;
    const float* x     = (const float*)d_in[0];
    // d_in[1] = grid : unused by the reference math
    const float* freqs = (const float*)d_in[2];
    const float* W1    = (const float*)d_in[3];
    const float* b1    = (const float*)d_in[4];
    const float* W2    = (const float*)d_in[5];
    const float* b2    = (const float*)d_in[6];
    const float* W3    = (const float*)d_in[7];
    const float* b3    = (const float*)d_in[8];
    float* out = (float*)d_out;

    // opt-in for >48KB dynamic smem (host-side, capture-safe, idempotent)
    static bool attr_set = false;
    if (!attr_set) {
        cudaFuncSetAttribute(domino_kernel,
                             cudaFuncAttributeMaxDynamicSharedMemorySize,
                             (int)SMEM_BYTES);
        attr_set = true;
    }

    // zero the output (8 * N_PTS floats = 786432 -> 196608 float4)
    const int n4 = (8 * N_PTS) / 4;
    zero_out_kernel<<<(n4 + 255) / 256, 256>>>(out, n4);

    domino_kernel<<<NTHRD / 128, 128, SMEM_BYTES>>>(x, freqs, W1, b1, W2, b2,
                                                    W3, b3, out);
}

// round 10
// speedup vs baseline: 1.4745x; 1.2632x over previous
#include <cuda_runtime.h>
#include <math.h>

// DoMINO point-MLP, TWO (point,neighbor) items per thread (same point),
// weight LDS shared between items (R6 structure, 3 CTAs/SM, no spill),
// activations vectorized with f32x2 packed math to cut fma-pipe slots.
// 33 -> 64 (gelu) -> 32 (gelu) -> 8 (tanh), masked sum over P=10,
// out (8,64,48,32) fp32, reduced via global RED into pre-zeroed d_out.

namespace {
constexpr int N_PTS = 98304;       // 64*48*32
constexpr int NB    = 10;
constexpr int NITEM = N_PTS * NB;  // 983040
constexpr int NTHRD = NITEM / 2;   // 491520 threads, 2 items each
// shared layout (floats); all offsets even -> 8B/16B aligned views OK
constexpr int OFF_W1 = 0;      // 33*64 = 2112
constexpr int OFF_B1 = 2112;   // 64
constexpr int OFF_W2 = 2176;   // 64*32 = 2048
constexpr int OFF_B2 = 4224;   // 32
constexpr int OFF_W3 = 4256;   // 32*8 = 256
constexpr int OFF_B3 = 4512;   // 8
constexpr int OFF_FR = 4520;   // 5 (+3 pad)
constexpr int SM_TOT = 4528;
}

typedef unsigned long long u64;

__device__ __forceinline__ u64 pk2(float x, float y) {
    u64 r;
    asm("mov.b64 %0, {%1, %2};" : "=l"(r) : "f"(x), "f"(y));
    return r;
}
__device__ __forceinline__ void up2(u64 a, float& x, float& y) {
    asm("mov.b64 {%0, %1}, %2;" : "=f"(x), "=f"(y) : "l"(a));
}
// packed dual fp32 FMA (accumulate form): d = a*b + d
__device__ __forceinline__ void fma2(u64& d, u64 a, u64 b) {
    asm("fma.rn.f32x2 %0, %1, %2, %0;" : "+l"(d) : "l"(a), "l"(b));
}
// packed dual fp32 FMA (3-operand): r = a*b + c
__device__ __forceinline__ u64 vfma2(u64 a, u64 b, u64 c) {
    u64 r;
    asm("fma.rn.f32x2 %0, %1, %2, %3;" : "=l"(r) : "l"(a), "l"(b), "l"(c));
    return r;
}
__device__ __forceinline__ u64 vmul2(u64 a, u64 b) {
    u64 r;
    asm("mul.rn.f32x2 %0, %1, %2;" : "=l"(r) : "l"(a), "l"(b));
    return r;
}
__device__ __forceinline__ u64 vadd2(u64 a, u64 b) {
    u64 r;
    asm("add.rn.f32x2 %0, %1, %2;" : "=l"(r) : "l"(a), "l"(b));
    return r;
}
__device__ __forceinline__ u64 C2(float c) { return pk2(c, c); }
// per-lane MUFU helpers on packed pairs
__device__ __forceinline__ u64 vrcp2(u64 a) {
    float x, y; up2(a, x, y);
    float rx, ry;
    asm("rcp.approx.f32 %0, %1;" : "=f"(rx) : "f"(x));
    asm("rcp.approx.f32 %0, %1;" : "=f"(ry) : "f"(y));
    return pk2(rx, ry);
}
__device__ __forceinline__ u64 vex2_2(u64 a) {
    float x, y; up2(a, x, y);
    float rx, ry;
    asm("ex2.approx.f32 %0, %1;" : "=f"(rx) : "f"(x));
    asm("ex2.approx.f32 %0, %1;" : "=f"(ry) : "f"(y));
    return pk2(rx, ry);
}

// Vector GELU on a packed pair, Abramowitz-Stegun 7.1.26 erf (|err|<=1.5e-7).
__device__ __forceinline__ u64 gelu2(u64 v) {
    const u64 ONE2 = C2(1.0f);
    u64 zz = vmul2(v, C2(0.70710678118654752440f));        // z pair
    u64 za = zz & 0x7FFFFFFF7FFFFFFFULL;                   // |z| (alu pipe)
    u64 t  = vrcp2(vfma2(C2(0.3275911f), za, ONE2));       // 1/(1+p|z|)
    u64 p  = vfma2(C2(-1.061405429f), t, C2(1.453152027f));// negated Horner -> -poly
    p = vfma2(p, t, C2(-1.421413741f));
    p = vfma2(p, t, C2(0.284496736f));
    p = vfma2(p, t, C2(-0.254829592f));
    p = vmul2(p, t);                                       // -poly
    u64 sq  = vmul2(za, za);
    u64 e   = vex2_2(vmul2(sq, C2(-1.4426950408889634f))); // exp(-z^2)
    u64 erf = vfma2(p, e, ONE2);                           // erf(|z|) >= 0
    erf |= (zz & 0x8000000080000000ULL);                   // copysign (alu pipe)
    return vmul2(vmul2(v, C2(0.5f)), vadd2(erf, ONE2));
}
// Vector tanh on a packed pair: 1 - 2/(exp(2x)+1); saturates correctly at +/-inf.
__device__ __forceinline__ u64 tanh2(u64 v) {
    const u64 ONE2 = C2(1.0f);
    u64 e = vex2_2(vmul2(v, C2(2.8853900817779268f)));     // exp(2x) = 2^(2x*log2e)
    u64 r = vrcp2(vadd2(e, ONE2));
    return vfma2(C2(-2.0f), r, ONE2);
}

__global__ void zero_out_kernel(float* __restrict__ out, int n4) {
    int i = blockIdx.x * blockDim.x + threadIdx.x;
    if (i < n4) reinterpret_cast<float4*>(out)[i] = make_float4(0.f, 0.f, 0.f, 0.f);
}

__global__ void __launch_bounds__(128, 3)
domino_kernel(const float* __restrict__ x,
              const float* __restrict__ freqs,
              const float* __restrict__ W1, const float* __restrict__ b1,
              const float* __restrict__ W2, const float* __restrict__ b2,
              const float* __restrict__ W3, const float* __restrict__ b3,
              float* __restrict__ out)
{
    __shared__ __align__(16) float sm[SM_TOT];

    // stage weights/biases/freqs into shared (broadcast source for the block)
    for (int i = threadIdx.x; i < 2112; i += blockDim.x) sm[OFF_W1 + i] = W1[i];
    for (int i = threadIdx.x; i < 64;   i += blockDim.x) sm[OFF_B1 + i] = b1[i];
    for (int i = threadIdx.x; i < 2048; i += blockDim.x) sm[OFF_W2 + i] = W2[i];
    for (int i = threadIdx.x; i < 32;   i += blockDim.x) sm[OFF_B2 + i] = b2[i];
    for (int i = threadIdx.x; i < 256;  i += blockDim.x) sm[OFF_W3 + i] = W3[i];
    for (int i = threadIdx.x; i < 8;    i += blockDim.x) sm[OFF_B3 + i] = b3[i];
    for (int i = threadIdx.x; i < 8;    i += blockDim.x) sm[OFF_FR + i] = (i < 5) ? freqs[i] : 0.0f;
    __syncthreads();

    const int t = blockIdx.x * blockDim.x + threadIdx.x;   // grid exact
    const int n = t / 5;                                   // output point index

    // items 2t and 2t+1 (same point): 6 consecutive floats, 8B aligned
    const float2* xv = reinterpret_cast<const float2*>(x + (size_t)t * 6);
    const float2 v0 = xv[0], v1 = xv[1], v2 = xv[2];
    const float xa0 = v0.x, xa1 = v0.y, xa2 = v1.x;
    const float xb0 = v1.y, xb1 = v2.x, xb2 = v2.y;
    const float ma = (fabsf(xa0) > 1e-6f) ? 1.0f : 0.0f;   // padded-neighbor masks
    const float mb = (fabsf(xb0) > 1e-6f) ? 1.0f : 0.0f;

    // double2 = 4 floats. Row sizes in double2: W1 row(64f)=16, W2 row(32f)=8, W3 row(8f)=2.
    const double2* W1v = reinterpret_cast<const double2*>(sm + OFF_W1);
    const u64*     b1v = reinterpret_cast<const u64*>(sm + OFF_B1);
    const double2* W2v = reinterpret_cast<const double2*>(sm + OFF_W2);
    const u64*     b2v = reinterpret_cast<const u64*>(sm + OFF_B2);
    const double2* W3v = reinterpret_cast<const double2*>(sm + OFF_W3);
    const u64*     b3v = reinterpret_cast<const u64*>(sm + OFF_B3);

    // ---- feature vectors (33 each), constant-indexed registers ----
    float fa[33], fb[33];
    fa[0] = xa0; fa[1] = xa1; fa[2] = xa2;
    fb[0] = xb0; fb[1] = xb1; fb[2] = xb2;
    {
        const float ca[3] = {xa0, xa1, xa2};
        const float cb[3] = {xb0, xb1, xb2};
#pragma unroll
        for (int m = 0; m < 5; m++) {
            const float frm = sm[OFF_FR + m];
#pragma unroll
            for (int d = 0; d < 3; d++) {
                float s, c;
                __sincosf(ca[d] * frm, &s, &c);
                fa[3  + m * 3 + d] = s;
                fa[18 + m * 3 + d] = c;
                __sincosf(cb[d] * frm, &s, &c);
                fb[3  + m * 3 + d] = s;
                fb[18 + m * 3 + d] = c;
            }
        }
    }

    // ---- layer 2 accumulators (32 outputs = 16 packed) per item ----
    u64 a2a[16], a2b[16];
#pragma unroll
    for (int kp = 0; kp < 16; kp++) { a2a[kp] = b2v[kp]; a2b[kp] = a2a[kp]; }

    // ---- layer 1 in 4 chunks of 16 outputs, streamed into layer 2 ----
#pragma unroll 1
    for (int jc = 0; jc < 4; jc++) {
        u64 c1a[8], c1b[8];
#pragma unroll
        for (int q = 0; q < 8; q++) { c1a[q] = b1v[jc * 8 + q]; c1b[q] = c1a[q]; }

#pragma unroll
        for (int i = 0; i < 33; i++) {
            const u64 ffa = pk2(fa[i], fa[i]);
            const u64 ffb = pk2(fb[i], fb[i]);
            const double2* wrow = W1v + i * 16 + jc * 4;
#pragma unroll
            for (int q = 0; q < 4; q++) {
                const double2 w = wrow[q];           // one LDS.128, serves both items
                const u64 wx = __double_as_longlong(w.x);
                const u64 wy = __double_as_longlong(w.y);
                fma2(c1a[2 * q],     ffa, wx);
                fma2(c1a[2 * q + 1], ffa, wy);
                fma2(c1b[2 * q],     ffb, wx);
                fma2(c1b[2 * q + 1], ffb, wy);
            }
        }

        // vector gelu the 16 chunk outputs of each item; stream into layer 2
#pragma unroll
        for (int q = 0; q < 8; q++) {
            float gau, gav, gbu, gbv;
            up2(gelu2(c1a[q]), gau, gav);
            up2(gelu2(c1b[q]), gbu, gbv);
            const u64 hau = pk2(gau, gau);
            const u64 hav = pk2(gav, gav);
            const u64 hbu = pk2(gbu, gbu);
            const u64 hbv = pk2(gbv, gbv);
            const int j0 = jc * 16 + 2 * q;
            const double2* w2a = W2v + (size_t)j0 * 8;   // row j0 (8 double2 = 32 floats)
            const double2* w2b = w2a + 8;                // row j0+1
#pragma unroll
            for (int kq = 0; kq < 8; kq++) {
                const double2 wa = w2a[kq];              // one LDS.128 serves both items
                const u64 wax = __double_as_longlong(wa.x);
                const u64 way = __double_as_longlong(wa.y);
                fma2(a2a[2 * kq],     hau, wax);
                fma2(a2a[2 * kq + 1], hau, way);
                fma2(a2b[2 * kq],     hbu, wax);
                fma2(a2b[2 * kq + 1], hbu, way);
                const double2 wb = w2b[kq];
                const u64 wbx = __double_as_longlong(wb.x);
                const u64 wby = __double_as_longlong(wb.y);
                fma2(a2a[2 * kq],     hav, wbx);
                fma2(a2a[2 * kq + 1], hav, wby);
                fma2(a2b[2 * kq],     hbv, wbx);
                fma2(a2b[2 * kq + 1], hbv, wby);
            }
        }
    }

    // ---- layer 3: consume a2 pairwise; h2 never materialized ----
    u64 a3a[4], a3b[4];
#pragma unroll
    for (int cp = 0; cp < 4; cp++) { a3a[cp] = b3v[cp]; a3b[cp] = a3a[cp]; }
#pragma unroll
    for (int q = 0; q < 16; q++) {
        float gau, gav, gbu, gbv;
        up2(gelu2(a2a[q]), gau, gav);
        up2(gelu2(a2b[q]), gbu, gbv);
        const u64 hau = pk2(gau, gau);
        const u64 hav = pk2(gav, gav);
        const u64 hbu = pk2(gbu, gbu);
        const u64 hbv = pk2(gbv, gbv);
        const int k0 = 2 * q;
        const double2* w3a = W3v + (size_t)k0 * 2;   // row k0 (2 double2 = 8 floats)
        const double2* w3b = w3a + 2;                // row k0+1
#pragma unroll
        for (int cq = 0; cq < 2; cq++) {
            const double2 wa = w3a[cq];
            const double2 wb = w3b[cq];
            const u64 wax = __double_as_longlong(wa.x);
            const u64 way = __double_as_longlong(wa.y);
            const u64 wbx = __double_as_longlong(wb.x);
            const u64 wby = __double_as_longlong(wb.y);
            fma2(a3a[2 * cq],     hau, wax);
            fma2(a3a[2 * cq + 1], hau, way);
            fma2(a3a[2 * cq],     hav, wbx);
            fma2(a3a[2 * cq + 1], hav, wby);
            fma2(a3b[2 * cq],     hbu, wax);
            fma2(a3b[2 * cq + 1], hbu, way);
            fma2(a3b[2 * cq],     hbv, wbx);
            fma2(a3b[2 * cq + 1], hbv, wby);
        }
    }

    // ---- vector tanh, mask-combine the two items, reduce via global RED ----
    const u64 ma2 = pk2(ma, ma);
    const u64 mb2 = pk2(mb, mb);
#pragma unroll
    for (int cp = 0; cp < 4; cp++) {
        const u64 ta = tanh2(a3a[cp]);
        const u64 tb = tanh2(a3b[cp]);
        u64 r = vmul2(ma2, ta);
        r = vfma2(mb2, tb, r);
        float r0, r1;
        up2(r, r0, r1);
        atomicAdd(&out[(size_t)(2 * cp)     * N_PTS + n], r0);
        atomicAdd(&out[(size_t)(2 * cp + 1) * N_PTS + n], r1);
    }
}

extern "C" void kernel_launch(void* const* d_in, const int* in_sizes, int n_in,
                              void* d_out, int out_size)
{
    (void)in_sizes; (void)n_in; (void)out_size;
    const float* x     = (const float*)d_in[0];
    // d_in[1] = grid : unused by the reference math
    const float* freqs = (const float*)d_in[2];
    const float* W1    = (const float*)d_in[3];
    const float* b1    = (const float*)d_in[4];
    const float* W2    = (const float*)d_in[5];
    const float* b2    = (const float*)d_in[6];
    const float* W3    = (const float*)d_in[7];
    const float* b3    = (const float*)d_in[8];
    float* out = (float*)d_out;

    // zero the output (8 * N_PTS floats = 786432 -> 196608 float4)
    const int n4 = (8 * N_PTS) / 4;
    zero_out_kernel<<<(n4 + 255) / 256, 256>>>(out, n4);

    domino_kernel<<<NTHRD / 128, 128>>>(x, freqs, W1, b1, W2, b2, W3, b3, out);
}

// round 11
// speedup vs baseline: 1.5579x; 1.0565x over previous
#include <cuda_runtime.h>
#include <math.h>

// DoMINO point-MLP, TWO (point,neighbor) items per thread (same point),
// weight LDS shared between items (3 CTAs/SM, no spill), f32x2 packed math
// everywhere; GELU uses 3-term A&S 7.1.25 erf with 0.5-folded constants.
// 33 -> 64 (gelu) -> 32 (gelu) -> 8 (tanh), masked sum over P=10,
// out (8,64,48,32) fp32, reduced via global RED into pre-zeroed d_out.

namespace {
constexpr int N_PTS = 98304;       // 64*48*32
constexpr int NB    = 10;
constexpr int NITEM = N_PTS * NB;  // 983040
constexpr int NTHRD = NITEM / 2;   // 491520 threads, 2 items each
// shared layout (floats); all offsets even -> 8B/16B aligned views OK
constexpr int OFF_W1 = 0;      // 33*64 = 2112
constexpr int OFF_B1 = 2112;   // 64
constexpr int OFF_W2 = 2176;   // 64*32 = 2048
constexpr int OFF_B2 = 4224;   // 32
constexpr int OFF_W3 = 4256;   // 32*8 = 256
constexpr int OFF_B3 = 4512;   // 8
constexpr int OFF_FR = 4520;   // 5 (+3 pad)
constexpr int SM_TOT = 4528;
}

typedef unsigned long long u64;

__device__ __forceinline__ u64 pk2(float x, float y) {
    u64 r;
    asm("mov.b64 %0, {%1, %2};" : "=l"(r) : "f"(x), "f"(y));
    return r;
}
__device__ __forceinline__ void up2(u64 a, float& x, float& y) {
    asm("mov.b64 {%0, %1}, %2;" : "=f"(x), "=f"(y) : "l"(a));
}
// packed dual fp32 FMA (accumulate form): d = a*b + d
__device__ __forceinline__ void fma2(u64& d, u64 a, u64 b) {
    asm("fma.rn.f32x2 %0, %1, %2, %0;" : "+l"(d) : "l"(a), "l"(b));
}
// packed dual fp32 FMA (3-operand): r = a*b + c
__device__ __forceinline__ u64 vfma2(u64 a, u64 b, u64 c) {
    u64 r;
    asm("fma.rn.f32x2 %0, %1, %2, %3;" : "=l"(r) : "l"(a), "l"(b), "l"(c));
    return r;
}
__device__ __forceinline__ u64 vmul2(u64 a, u64 b) {
    u64 r;
    asm("mul.rn.f32x2 %0, %1, %2;" : "=l"(r) : "l"(a), "l"(b));
    return r;
}
__device__ __forceinline__ u64 vadd2(u64 a, u64 b) {
    u64 r;
    asm("add.rn.f32x2 %0, %1, %2;" : "=l"(r) : "l"(a), "l"(b));
    return r;
}
__device__ __forceinline__ u64 C2(float c) { return pk2(c, c); }
// per-lane MUFU helpers on packed pairs
__device__ __forceinline__ u64 vrcp2(u64 a) {
    float x, y; up2(a, x, y);
    float rx, ry;
    asm("rcp.approx.f32 %0, %1;" : "=f"(rx) : "f"(x));
    asm("rcp.approx.f32 %0, %1;" : "=f"(ry) : "f"(y));
    return pk2(rx, ry);
}
__device__ __forceinline__ u64 vex2_2(u64 a) {
    float x, y; up2(a, x, y);
    float rx, ry;
    asm("ex2.approx.f32 %0, %1;" : "=f"(rx) : "f"(x));
    asm("ex2.approx.f32 %0, %1;" : "=f"(ry) : "f"(y));
    return pk2(rx, ry);
}

// Vector GELU, Abramowitz-Stegun 7.1.25 erf (3-term, |err|<=2.5e-5),
// with both 0.5 factors folded into the polynomial constants.
// gelu(v) = v * (0.5 + copysign(0.5*erf(|v|/sqrt2), v))
__device__ __forceinline__ u64 gelu2(u64 v) {
    const u64 ONE2 = C2(1.0f);
    const u64 sgn = v & 0x8000000080000000ULL;              // alu
    const u64 va  = v & 0x7FFFFFFF7FFFFFFFULL;              // alu
    u64 za = vmul2(va, C2(0.70710678118654752440f));        // |z|
    u64 t  = vrcp2(vfma2(C2(0.47047f), za, ONE2));          // 1/(1+p|z|)
    // q = -(a1 t + a2 t^2 + a3 t^3)/2, coefficients pre-halved & negated
    u64 q  = vfma2(C2(-0.3739278f), t, C2(0.0479399f));
    q = vfma2(q, t, C2(-0.1740121f));
    q = vmul2(q, t);
    u64 e  = vex2_2(vmul2(vmul2(za, za), C2(-1.4426950408889634f))); // exp(-z^2)
    u64 erfh = vfma2(q, e, C2(0.5f));                       // 0.5*erf(|z|) >= 0
    erfh |= sgn;                                            // alu: exact +/-
    return vmul2(v, vadd2(erfh, C2(0.5f)));
}
// Vector tanh on a packed pair: 1 - 2/(exp(2x)+1); saturates correctly at +/-inf.
__device__ __forceinline__ u64 tanh2(u64 v) {
    const u64 ONE2 = C2(1.0f);
    u64 e = vex2_2(vmul2(v, C2(2.8853900817779268f)));      // exp(2x) = 2^(2x*log2e)
    u64 r = vrcp2(vadd2(e, ONE2));
    return vfma2(C2(-2.0f), r, ONE2);
}

__global__ void zero_out_kernel(float* __restrict__ out, int n4) {
    int i = blockIdx.x * blockDim.x + threadIdx.x;
    if (i < n4) reinterpret_cast<float4*>(out)[i] = make_float4(0.f, 0.f, 0.f, 0.f);
}

__global__ void __launch_bounds__(128, 3)
domino_kernel(const float* __restrict__ x,
              const float* __restrict__ freqs,
              const float* __restrict__ W1, const float* __restrict__ b1,
              const float* __restrict__ W2, const float* __restrict__ b2,
              const float* __restrict__ W3, const float* __restrict__ b3,
              float* __restrict__ out)
{
    __shared__ __align__(16) float sm[SM_TOT];

    // stage weights/biases/freqs into shared (broadcast source for the block)
    for (int i = threadIdx.x; i < 2112; i += blockDim.x) sm[OFF_W1 + i] = W1[i];
    for (int i = threadIdx.x; i < 64;   i += blockDim.x) sm[OFF_B1 + i] = b1[i];
    for (int i = threadIdx.x; i < 2048; i += blockDim.x) sm[OFF_W2 + i] = W2[i];
    for (int i = threadIdx.x; i < 32;   i += blockDim.x) sm[OFF_B2 + i] = b2[i];
    for (int i = threadIdx.x; i < 256;  i += blockDim.x) sm[OFF_W3 + i] = W3[i];
    for (int i = threadIdx.x; i < 8;    i += blockDim.x) sm[OFF_B3 + i] = b3[i];
    for (int i = threadIdx.x; i < 8;    i += blockDim.x) sm[OFF_FR + i] = (i < 5) ? freqs[i] : 0.0f;
    __syncthreads();

    const int t = blockIdx.x * blockDim.x + threadIdx.x;   // grid exact
    const int n = t / 5;                                   // output point index

    // items 2t and 2t+1 (same point): 6 consecutive floats, 8B aligned
    const float2* xv = reinterpret_cast<const float2*>(x + (size_t)t * 6);
    const float2 v0 = xv[0], v1 = xv[1], v2 = xv[2];
    const float xa0 = v0.x, xa1 = v0.y, xa2 = v1.x;
    const float xb0 = v1.y, xb1 = v2.x, xb2 = v2.y;
    const float ma = (fabsf(xa0) > 1e-6f) ? 1.0f : 0.0f;   // padded-neighbor masks
    const float mb = (fabsf(xb0) > 1e-6f) ? 1.0f : 0.0f;

    // double2 = 4 floats. Row sizes in double2: W1 row(64f)=16, W2 row(32f)=8, W3 row(8f)=2.
    const double2* W1v = reinterpret_cast<const double2*>(sm + OFF_W1);
    const u64*     b1v = reinterpret_cast<const u64*>(sm + OFF_B1);
    const double2* W2v = reinterpret_cast<const double2*>(sm + OFF_W2);
    const u64*     b2v = reinterpret_cast<const u64*>(sm + OFF_B2);
    const double2* W3v = reinterpret_cast<const double2*>(sm + OFF_W3);
    const u64*     b3v = reinterpret_cast<const u64*>(sm + OFF_B3);

    // ---- feature vectors (33 each), constant-indexed registers ----
    float fa[33], fb[33];
    fa[0] = xa0; fa[1] = xa1; fa[2] = xa2;
    fb[0] = xb0; fb[1] = xb1; fb[2] = xb2;
    {
        const float ca[3] = {xa0, xa1, xa2};
        const float cb[3] = {xb0, xb1, xb2};
#pragma unroll
        for (int m = 0; m < 5; m++) {
            const float frm = sm[OFF_FR + m];
#pragma unroll
            for (int d = 0; d < 3; d++) {
                float s, c;
                __sincosf(ca[d] * frm, &s, &c);
                fa[3  + m * 3 + d] = s;
                fa[18 + m * 3 + d] = c;
                __sincosf(cb[d] * frm, &s, &c);
                fb[3  + m * 3 + d] = s;
                fb[18 + m * 3 + d] = c;
            }
        }
    }

    // ---- layer 2 accumulators (32 outputs = 16 packed) per item ----
    u64 a2a[16], a2b[16];
#pragma unroll
    for (int kp = 0; kp < 16; kp++) { a2a[kp] = b2v[kp]; a2b[kp] = a2a[kp]; }

    // ---- layer 1 in 4 chunks of 16 outputs, streamed into layer 2 ----
#pragma unroll 1
    for (int jc = 0; jc < 4; jc++) {
        u64 c1a[8], c1b[8];
#pragma unroll
        for (int q = 0; q < 8; q++) { c1a[q] = b1v[jc * 8 + q]; c1b[q] = c1a[q]; }

#pragma unroll
        for (int i = 0; i < 33; i++) {
            const u64 ffa = pk2(fa[i], fa[i]);
            const u64 ffb = pk2(fb[i], fb[i]);
            const double2* wrow = W1v + i * 16 + jc * 4;
#pragma unroll
            for (int q = 0; q < 4; q++) {
                const double2 w = wrow[q];           // one LDS.128, serves both items
                const u64 wx = __double_as_longlong(w.x);
                const u64 wy = __double_as_longlong(w.y);
                fma2(c1a[2 * q],     ffa, wx);
                fma2(c1a[2 * q + 1], ffa, wy);
                fma2(c1b[2 * q],     ffb, wx);
                fma2(c1b[2 * q + 1], ffb, wy);
            }
        }

        // vector gelu the 16 chunk outputs of each item; stream into layer 2
#pragma unroll
        for (int q = 0; q < 8; q++) {
            float gau, gav, gbu, gbv;
            up2(gelu2(c1a[q]), gau, gav);
            up2(gelu2(c1b[q]), gbu, gbv);
            const u64 hau = pk2(gau, gau);
            const u64 hav = pk2(gav, gav);
            const u64 hbu = pk2(gbu, gbu);
            const u64 hbv = pk2(gbv, gbv);
            const int j0 = jc * 16 + 2 * q;
            const double2* w2a = W2v + (size_t)j0 * 8;   // row j0 (8 double2 = 32 floats)
            const double2* w2b = w2a + 8;                // row j0+1
#pragma unroll
            for (int kq = 0; kq < 8; kq++) {
                const double2 wa = w2a[kq];              // one LDS.128 serves both items
                const u64 wax = __double_as_longlong(wa.x);
                const u64 way = __double_as_longlong(wa.y);
                fma2(a2a[2 * kq],     hau, wax);
                fma2(a2a[2 * kq + 1], hau, way);
                fma2(a2b[2 * kq],     hbu, wax);
                fma2(a2b[2 * kq + 1], hbu, way);
                const double2 wb = w2b[kq];
                const u64 wbx = __double_as_longlong(wb.x);
                const u64 wby = __double_as_longlong(wb.y);
                fma2(a2a[2 * kq],     hav, wbx);
                fma2(a2a[2 * kq + 1], hav, wby);
                fma2(a2b[2 * kq],     hbv, wbx);
                fma2(a2b[2 * kq + 1], hbv, wby);
            }
        }
    }

    // ---- layer 3: consume a2 pairwise; h2 never materialized ----
    u64 a3a[4], a3b[4];
#pragma unroll
    for (int cp = 0; cp < 4; cp++) { a3a[cp] = b3v[cp]; a3b[cp] = a3a[cp]; }
#pragma unroll
    for (int q = 0; q < 16; q++) {
        float gau, gav, gbu, gbv;
        up2(gelu2(a2a[q]), gau, gav);
        up2(gelu2(a2b[q]), gbu, gbv);
        const u64 hau = pk2(gau, gau);
        const u64 hav = pk2(gav, gav);
        const u64 hbu = pk2(gbu, gbu);
        const u64 hbv = pk2(gbv, gbv);
        const int k0 = 2 * q;
        const double2* w3a = W3v + (size_t)k0 * 2;   // row k0 (2 double2 = 8 floats)
        const double2* w3b = w3a + 2;                // row k0+1
#pragma unroll
        for (int cq = 0; cq < 2; cq++) {
            const double2 wa = w3a[cq];
            const double2 wb = w3b[cq];
            const u64 wax = __double_as_longlong(wa.x);
            const u64 way = __double_as_longlong(wa.y);
            const u64 wbx = __double_as_longlong(wb.x);
            const u64 wby = __double_as_longlong(wb.y);
            fma2(a3a[2 * cq],     hau, wax);
            fma2(a3a[2 * cq + 1], hau, way);
            fma2(a3a[2 * cq],     hav, wbx);
            fma2(a3a[2 * cq + 1], hav, wby);
            fma2(a3b[2 * cq],     hbu, wax);
            fma2(a3b[2 * cq + 1], hbu, way);
            fma2(a3b[2 * cq],     hbv, wbx);
            fma2(a3b[2 * cq + 1], hbv, wby);
        }
    }

    // ---- vector tanh, mask-combine the two items, reduce via global RED ----
    const u64 ma2 = pk2(ma, ma);
    const u64 mb2 = pk2(mb, mb);
#pragma unroll
    for (int cp = 0; cp < 4; cp++) {
        const u64 ta = tanh2(a3a[cp]);
        const u64 tb = tanh2(a3b[cp]);
        u64 r = vmul2(ma2, ta);
        r = vfma2(mb2, tb, r);
        float r0, r1;
        up2(r, r0, r1);
        atomicAdd(&out[(size_t)(2 * cp)     * N_PTS + n], r0);
        atomicAdd(&out[(size_t)(2 * cp + 1) * N_PTS + n], r1);
    }
}

extern "C" void kernel_launch(void* const* d_in, const int* in_sizes, int n_in,
                              void* d_out, int out_size)
{
    (void)in_sizes; (void)n_in; (void)out_size;
    const float* x     = (const float*)d_in[0];
    // d_in[1] = grid : unused by the reference math
    const float* freqs = (const float*)d_in[2];
    const float* W1    = (const float*)d_in[3];
    const float* b1    = (const float*)d_in[4];
    const float* W2    = (const float*)d_in[5];
    const float* b2    = (const float*)d_in[6];
    const float* W3    = (const float*)d_in[7];
    const float* b3    = (const float*)d_in[8];
    float* out = (float*)d_out;

    // zero the output (8 * N_PTS floats = 786432 -> 196608 float4)
    const int n4 = (8 * N_PTS) / 4;
    zero_out_kernel<<<(n4 + 255) / 256, 256>>>(out, n4);

    domino_kernel<<<NTHRD / 128, 128>>>(x, freqs, W1, b1, W2, b2, W3, b3, out);
}

// round 12
// speedup vs baseline: 1.6318x; 1.0474x over previous
#include <cuda_runtime.h>
#include <math.h>

// DoMINO point-MLP, TWO (point,neighbor) items per thread (same point),
// weight LDS shared between items (3 CTAs/SM, no spill), f32x2 packed math;
// GELU via A&S 7.1.27 rational erf (1 MUFU), packed sincos args.
// 33 -> 64 (gelu) -> 32 (gelu) -> 8 (tanh), masked sum over P=10,
// out (8,64,48,32) fp32, reduced via global RED into pre-zeroed d_out.

namespace {
constexpr int N_PTS = 98304;       // 64*48*32
constexpr int NB    = 10;
constexpr int NITEM = N_PTS * NB;  // 983040
constexpr int NTHRD = NITEM / 2;   // 491520 threads, 2 items each
// shared layout (floats); all offsets even -> 8B/16B aligned views OK
constexpr int OFF_W1 = 0;      // 33*64 = 2112
constexpr int OFF_B1 = 2112;   // 64
constexpr int OFF_W2 = 2176;   // 64*32 = 2048
constexpr int OFF_B2 = 4224;   // 32
constexpr int OFF_W3 = 4256;   // 32*8 = 256
constexpr int OFF_B3 = 4512;   // 8
constexpr int OFF_FR = 4520;   // 5 (+3 pad)
constexpr int SM_TOT = 4528;
}

typedef unsigned long long u64;

__device__ __forceinline__ u64 pk2(float x, float y) {
    u64 r;
    asm("mov.b64 %0, {%1, %2};" : "=l"(r) : "f"(x), "f"(y));
    return r;
}
__device__ __forceinline__ void up2(u64 a, float& x, float& y) {
    asm("mov.b64 {%0, %1}, %2;" : "=f"(x), "=f"(y) : "l"(a));
}
// packed dual fp32 FMA (accumulate form): d = a*b + d
__device__ __forceinline__ void fma2(u64& d, u64 a, u64 b) {
    asm("fma.rn.f32x2 %0, %1, %2, %0;" : "+l"(d) : "l"(a), "l"(b));
}
// packed dual fp32 FMA (3-operand): r = a*b + c
__device__ __forceinline__ u64 vfma2(u64 a, u64 b, u64 c) {
    u64 r;
    asm("fma.rn.f32x2 %0, %1, %2, %3;" : "=l"(r) : "l"(a), "l"(b), "l"(c));
    return r;
}
__device__ __forceinline__ u64 vmul2(u64 a, u64 b) {
    u64 r;
    asm("mul.rn.f32x2 %0, %1, %2;" : "=l"(r) : "l"(a), "l"(b));
    return r;
}
__device__ __forceinline__ u64 vadd2(u64 a, u64 b) {
    u64 r;
    asm("add.rn.f32x2 %0, %1, %2;" : "=l"(r) : "l"(a), "l"(b));
    return r;
}
__device__ __forceinline__ u64 C2(float c) { return pk2(c, c); }
// per-lane MUFU helpers on packed pairs
__device__ __forceinline__ u64 vrcp2(u64 a) {
    float x, y; up2(a, x, y);
    float rx, ry;
    asm("rcp.approx.f32 %0, %1;" : "=f"(rx) : "f"(x));
    asm("rcp.approx.f32 %0, %1;" : "=f"(ry) : "f"(y));
    return pk2(rx, ry);
}
__device__ __forceinline__ u64 vex2_2(u64 a) {
    float x, y; up2(a, x, y);
    float rx, ry;
    asm("ex2.approx.f32 %0, %1;" : "=f"(rx) : "f"(x));
    asm("ex2.approx.f32 %0, %1;" : "=f"(ry) : "f"(y));
    return pk2(rx, ry);
}

// Vector GELU, A&S 7.1.27 rational erf: erf(z) ~= 1 - 1/p(z)^4, |err|<=5e-4.
// gelu(v) = v * (0.5 + copysign(0.5*erf(|v|/sqrt2), v)); one MUFU (rcp).
__device__ __forceinline__ u64 gelu2(u64 v) {
    const u64 ONE2 = C2(1.0f);
    const u64 sgn = v & 0x8000000080000000ULL;              // alu
    const u64 va  = v & 0x7FFFFFFF7FFFFFFFULL;              // alu
    u64 za = vmul2(va, C2(0.70710678118654752440f));        // |z|
    u64 p  = vfma2(C2(0.078108f), za, C2(0.000972f));
    p = vfma2(p, za, C2(0.230389f));
    p = vfma2(p, za, C2(0.278393f));
    p = vfma2(p, za, ONE2);                                 // p >= 1
    u64 p2 = vmul2(p, p);
    u64 p4 = vmul2(p2, p2);
    u64 r  = vrcp2(p4);                                     // 1/p^4
    u64 erfh = vfma2(C2(-0.5f), r, C2(0.5f));               // 0.5*erf(|z|) >= 0
    erfh |= sgn;                                            // alu: exact +/-
    return vmul2(v, vadd2(erfh, C2(0.5f)));
}
// Vector tanh on a packed pair: 1 - 2/(exp(2x)+1); saturates correctly at +/-inf.
__device__ __forceinline__ u64 tanh2(u64 v) {
    const u64 ONE2 = C2(1.0f);
    u64 e = vex2_2(vmul2(v, C2(2.8853900817779268f)));      // exp(2x) = 2^(2x*log2e)
    u64 r = vrcp2(vadd2(e, ONE2));
    return vfma2(C2(-2.0f), r, ONE2);
}

__global__ void zero_out_kernel(float* __restrict__ out, int n4) {
    int i = blockIdx.x * blockDim.x + threadIdx.x;
    if (i < n4) reinterpret_cast<float4*>(out)[i] = make_float4(0.f, 0.f, 0.f, 0.f);
}

__global__ void __launch_bounds__(128, 3)
domino_kernel(const float* __restrict__ x,
              const float* __restrict__ freqs,
              const float* __restrict__ W1, const float* __restrict__ b1,
              const float* __restrict__ W2, const float* __restrict__ b2,
              const float* __restrict__ W3, const float* __restrict__ b3,
              float* __restrict__ out)
{
    __shared__ __align__(16) float sm[SM_TOT];

    // stage weights/biases/freqs into shared (broadcast source for the block)
    for (int i = threadIdx.x; i < 2112; i += blockDim.x) sm[OFF_W1 + i] = W1[i];
    for (int i = threadIdx.x; i < 64;   i += blockDim.x) sm[OFF_B1 + i] = b1[i];
    for (int i = threadIdx.x; i < 2048; i += blockDim.x) sm[OFF_W2 + i] = W2[i];
    for (int i = threadIdx.x; i < 32;   i += blockDim.x) sm[OFF_B2 + i] = b2[i];
    for (int i = threadIdx.x; i < 256;  i += blockDim.x) sm[OFF_W3 + i] = W3[i];
    for (int i = threadIdx.x; i < 8;    i += blockDim.x) sm[OFF_B3 + i] = b3[i];
    for (int i = threadIdx.x; i < 8;    i += blockDim.x) sm[OFF_FR + i] = (i < 5) ? freqs[i] : 0.0f;
    __syncthreads();

    const int t = blockIdx.x * blockDim.x + threadIdx.x;   // grid exact
    const int n = t / 5;                                   // output point index

    // items 2t and 2t+1 (same point): 6 consecutive floats, 8B aligned
    const float2* xv = reinterpret_cast<const float2*>(x + (size_t)t * 6);
    const float2 v0 = xv[0], v1 = xv[1], v2 = xv[2];
    const float xa0 = v0.x, xa1 = v0.y, xa2 = v1.x;
    const float xb0 = v1.y, xb1 = v2.x, xb2 = v2.y;
    const float ma = (fabsf(xa0) > 1e-6f) ? 1.0f : 0.0f;   // padded-neighbor masks
    const float mb = (fabsf(xb0) > 1e-6f) ? 1.0f : 0.0f;

    // double2 = 4 floats. Row sizes in double2: W1 row(64f)=16, W2 row(32f)=8, W3 row(8f)=2.
    const double2* W1v = reinterpret_cast<const double2*>(sm + OFF_W1);
    const u64*     b1v = reinterpret_cast<const u64*>(sm + OFF_B1);
    const double2* W2v = reinterpret_cast<const double2*>(sm + OFF_W2);
    const u64*     b2v = reinterpret_cast<const u64*>(sm + OFF_B2);
    const double2* W3v = reinterpret_cast<const double2*>(sm + OFF_W3);
    const u64*     b3v = reinterpret_cast<const u64*>(sm + OFF_B3);

    // ---- feature vectors (33 each); sincos args packed as (a,b) pairs ----
    float fa[33], fb[33];
    fa[0] = xa0; fa[1] = xa1; fa[2] = xa2;
    fb[0] = xb0; fb[1] = xb1; fb[2] = xb2;
    {
        const u64 cab[3] = {pk2(xa0, xb0), pk2(xa1, xb1), pk2(xa2, xb2)};
#pragma unroll
        for (int m = 0; m < 5; m++) {
            const u64 frm2 = C2(sm[OFF_FR + m]);
#pragma unroll
            for (int d = 0; d < 3; d++) {
                float ta_, tb_;
                up2(vmul2(cab[d], frm2), ta_, tb_);   // one packed mul for both args
                float s, c;
                __sincosf(ta_, &s, &c);
                fa[3  + m * 3 + d] = s;
                fa[18 + m * 3 + d] = c;
                __sincosf(tb_, &s, &c);
                fb[3  + m * 3 + d] = s;
                fb[18 + m * 3 + d] = c;
            }
        }
    }

    // ---- layer 2 accumulators (32 outputs = 16 packed) per item ----
    u64 a2a[16], a2b[16];
#pragma unroll
    for (int kp = 0; kp < 16; kp++) { a2a[kp] = b2v[kp]; a2b[kp] = a2a[kp]; }

    // ---- layer 1 in 4 chunks of 16 outputs, streamed into layer 2 ----
#pragma unroll 1
    for (int jc = 0; jc < 4; jc++) {
        u64 c1a[8], c1b[8];
#pragma unroll
        for (int q = 0; q < 8; q++) { c1a[q] = b1v[jc * 8 + q]; c1b[q] = c1a[q]; }

#pragma unroll
        for (int i = 0; i < 33; i++) {
            const u64 ffa = pk2(fa[i], fa[i]);
            const u64 ffb = pk2(fb[i], fb[i]);
            const double2* wrow = W1v + i * 16 + jc * 4;
#pragma unroll
            for (int q = 0; q < 4; q++) {
                const double2 w = wrow[q];           // one LDS.128, serves both items
                const u64 wx = __double_as_longlong(w.x);
                const u64 wy = __double_as_longlong(w.y);
                fma2(c1a[2 * q],     ffa, wx);
                fma2(c1a[2 * q + 1], ffa, wy);
                fma2(c1b[2 * q],     ffb, wx);
                fma2(c1b[2 * q + 1], ffb, wy);
            }
        }

        // vector gelu the 16 chunk outputs of each item; stream into layer 2
#pragma unroll
        for (int q = 0; q < 8; q++) {
            float gau, gav, gbu, gbv;
            up2(gelu2(c1a[q]), gau, gav);
            up2(gelu2(c1b[q]), gbu, gbv);
            const u64 hau = pk2(gau, gau);
            const u64 hav = pk2(gav, gav);
            const u64 hbu = pk2(gbu, gbu);
            const u64 hbv = pk2(gbv, gbv);
            const int j0 = jc * 16 + 2 * q;
            const double2* w2a = W2v + (size_t)j0 * 8;   // row j0 (8 double2 = 32 floats)
            const double2* w2b = w2a + 8;                // row j0+1
#pragma unroll
            for (int kq = 0; kq < 8; kq++) {
                const double2 wa = w2a[kq];              // one LDS.128 serves both items
                const u64 wax = __double_as_longlong(wa.x);
                const u64 way = __double_as_longlong(wa.y);
                fma2(a2a[2 * kq],     hau, wax);
                fma2(a2a[2 * kq + 1], hau, way);
                fma2(a2b[2 * kq],     hbu, wax);
                fma2(a2b[2 * kq + 1], hbu, way);
                const double2 wb = w2b[kq];
                const u64 wbx = __double_as_longlong(wb.x);
                const u64 wby = __double_as_longlong(wb.y);
                fma2(a2a[2 * kq],     hav, wbx);
                fma2(a2a[2 * kq + 1], hav, wby);
                fma2(a2b[2 * kq],     hbv, wbx);
                fma2(a2b[2 * kq + 1], hbv, wby);
            }
        }
    }

    // ---- layer 3: consume a2 pairwise; h2 never materialized ----
    u64 a3a[4], a3b[4];
#pragma unroll
    for (int cp = 0; cp < 4; cp++) { a3a[cp] = b3v[cp]; a3b[cp] = a3a[cp]; }
#pragma unroll
    for (int q = 0; q < 16; q++) {
        float gau, gav, gbu, gbv;
        up2(gelu2(a2a[q]), gau, gav);
        up2(gelu2(a2b[q]), gbu, gbv);
        const u64 hau = pk2(gau, gau);
        const u64 hav = pk2(gav, gav);
        const u64 hbu = pk2(gbu, gbu);
        const u64 hbv = pk2(gbv, gbv);
        const int k0 = 2 * q;
        const double2* w3a = W3v + (size_t)k0 * 2;   // row k0 (2 double2 = 8 floats)
        const double2* w3b = w3a + 2;                // row k0+1
#pragma unroll
        for (int cq = 0; cq < 2; cq++) {
            const double2 wa = w3a[cq];
            const double2 wb = w3b[cq];
            const u64 wax = __double_as_longlong(wa.x);
            const u64 way = __double_as_longlong(wa.y);
            const u64 wbx = __double_as_longlong(wb.x);
            const u64 wby = __double_as_longlong(wb.y);
            fma2(a3a[2 * cq],     hau, wax);
            fma2(a3a[2 * cq + 1], hau, way);
            fma2(a3a[2 * cq],     hav, wbx);
            fma2(a3a[2 * cq + 1], hav, wby);
            fma2(a3b[2 * cq],     hbu, wax);
            fma2(a3b[2 * cq + 1], hbu, way);
            fma2(a3b[2 * cq],     hbv, wbx);
            fma2(a3b[2 * cq + 1], hbv, wby);
        }
    }

    // ---- vector tanh, mask-combine the two items, reduce via global RED ----
    const u64 ma2 = pk2(ma, ma);
    const u64 mb2 = pk2(mb, mb);
#pragma unroll
    for (int cp = 0; cp < 4; cp++) {
        const u64 ta = tanh2(a3a[cp]);
        const u64 tb = tanh2(a3b[cp]);
        u64 r = vmul2(ma2, ta);
        r = vfma2(mb2, tb, r);
        float r0, r1;
        up2(r, r0, r1);
        atomicAdd(&out[(size_t)(2 * cp)     * N_PTS + n], r0);
        atomicAdd(&out[(size_t)(2 * cp + 1) * N_PTS + n], r1);
    }
}

extern "C" void kernel_launch(void* const* d_in, const int* in_sizes, int n_in,
                              void* d_out, int out_size)
{
    (void)in_sizes; (void)n_in; (void)out_size;
    const float* x     = (const float*)d_in[0];
    // d_in[1] = grid : unused by the reference math
    const float* freqs = (const float*)d_in[2];
    const float* W1    = (const float*)d_in[3];
    const float* b1    = (const float*)d_in[4];
    const float* W2    = (const float*)d_in[5];
    const float* b2    = (const float*)d_in[6];
    const float* W3    = (const float*)d_in[7];
    const float* b3    = (const float*)d_in[8];
    float* out = (float*)d_out;

    // zero the output (8 * N_PTS floats = 786432 -> 196608 float4)
    const int n4 = (8 * N_PTS) / 4;
    zero_out_kernel<<<(n4 + 255) / 256, 256>>>(out, n4);

    domino_kernel<<<NTHRD / 128, 128>>>(x, freqs, W1, b1, W2, b2, W3, b3, out);
}

// round 13
// speedup vs baseline: 1.6597x; 1.0171x over previous
#include <cuda_runtime.h>
#include <math.h>

// DoMINO point-MLP, TWO (point,neighbor) items per thread (same point),
// weight LDS shared between items (3 CTAs/SM, no spill), f32x2 packed math;
// GELU via A&S 7.1.27 rational erf with 1/sqrt2 folded into coefficients;
// feature broadcasts pre-packed once (no per-chunk mov.b64 repacking).
// 33 -> 64 (gelu) -> 32 (gelu) -> 8 (tanh), masked sum over P=10,
// out (8,64,48,32) fp32, reduced via global RED into pre-zeroed d_out.

namespace {
constexpr int N_PTS = 98304;       // 64*48*32
constexpr int NB    = 10;
constexpr int NITEM = N_PTS * NB;  // 983040
constexpr int NTHRD = NITEM / 2;   // 491520 threads, 2 items each
// shared layout (floats); all offsets even -> 8B/16B aligned views OK
constexpr int OFF_W1 = 0;      // 33*64 = 2112
constexpr int OFF_B1 = 2112;   // 64
constexpr int OFF_W2 = 2176;   // 64*32 = 2048
constexpr int OFF_B2 = 4224;   // 32
constexpr int OFF_W3 = 4256;   // 32*8 = 256
constexpr int OFF_B3 = 4512;   // 8
constexpr int OFF_FR = 4520;   // 5 (+3 pad)
constexpr int SM_TOT = 4528;
}

typedef unsigned long long u64;

__device__ __forceinline__ u64 pk2(float x, float y) {
    u64 r;
    asm("mov.b64 %0, {%1, %2};" : "=l"(r) : "f"(x), "f"(y));
    return r;
}
__device__ __forceinline__ void up2(u64 a, float& x, float& y) {
    asm("mov.b64 {%0, %1}, %2;" : "=f"(x), "=f"(y) : "l"(a));
}
// packed dual fp32 FMA (accumulate form): d = a*b + d
__device__ __forceinline__ void fma2(u64& d, u64 a, u64 b) {
    asm("fma.rn.f32x2 %0, %1, %2, %0;" : "+l"(d) : "l"(a), "l"(b));
}
// packed dual fp32 FMA (3-operand): r = a*b + c
__device__ __forceinline__ u64 vfma2(u64 a, u64 b, u64 c) {
    u64 r;
    asm("fma.rn.f32x2 %0, %1, %2, %3;" : "=l"(r) : "l"(a), "l"(b), "l"(c));
    return r;
}
__device__ __forceinline__ u64 vmul2(u64 a, u64 b) {
    u64 r;
    asm("mul.rn.f32x2 %0, %1, %2;" : "=l"(r) : "l"(a), "l"(b));
    return r;
}
__device__ __forceinline__ u64 vadd2(u64 a, u64 b) {
    u64 r;
    asm("add.rn.f32x2 %0, %1, %2;" : "=l"(r) : "l"(a), "l"(b));
    return r;
}
__device__ __forceinline__ u64 C2(float c) { return pk2(c, c); }
// per-lane MUFU helpers on packed pairs
__device__ __forceinline__ u64 vrcp2(u64 a) {
    float x, y; up2(a, x, y);
    float rx, ry;
    asm("rcp.approx.f32 %0, %1;" : "=f"(rx) : "f"(x));
    asm("rcp.approx.f32 %0, %1;" : "=f"(ry) : "f"(y));
    return pk2(rx, ry);
}
__device__ __forceinline__ u64 vex2_2(u64 a) {
    float x, y; up2(a, x, y);
    float rx, ry;
    asm("ex2.approx.f32 %0, %1;" : "=f"(rx) : "f"(x));
    asm("ex2.approx.f32 %0, %1;" : "=f"(ry) : "f"(y));
    return pk2(rx, ry);
}

// Vector GELU, A&S 7.1.27 rational erf: erf(z) ~= 1 - 1/p(z)^4, |err|<=5e-4,
// with z = |v|/sqrt2 substituted into the polynomial (coeffs pre-scaled):
//   p = 1 + c1|v| + c2|v|^2 + c3|v|^3 + c4|v|^4,  c_k = a_k * (1/sqrt2)^k
// gelu(v) = v * (0.5 + copysign(0.5*erf, v)); one MUFU (rcp), 9 fma-class ops.
__device__ __forceinline__ u64 gelu2(u64 v) {
    const u64 ONE2 = C2(1.0f);
    const u64 sgn = v & 0x8000000080000000ULL;              // alu
    const u64 va  = v & 0x7FFFFFFF7FFFFFFFULL;              // alu
    u64 p  = vfma2(C2(0.019527000f), va, C2(0.00034366f)); // c4*|v| + c3
    p = vfma2(p, va, C2(0.11519450f));                      // + c2
    p = vfma2(p, va, C2(0.19686071f));                      // + c1
    p = vfma2(p, va, ONE2);                                 // p >= 1
    u64 p2 = vmul2(p, p);
    u64 p4 = vmul2(p2, p2);
    u64 r  = vrcp2(p4);                                     // 1/p^4
    u64 erfh = vfma2(C2(-0.5f), r, C2(0.5f));               // 0.5*erf(|z|) >= 0
    erfh |= sgn;                                            // alu: exact +/-
    return vmul2(v, vadd2(erfh, C2(0.5f)));
}
// Vector tanh on a packed pair: 1 - 2/(exp(2x)+1); saturates correctly at +/-inf.
__device__ __forceinline__ u64 tanh2(u64 v) {
    const u64 ONE2 = C2(1.0f);
    u64 e = vex2_2(vmul2(v, C2(2.8853900817779268f)));      // exp(2x) = 2^(2x*log2e)
    u64 r = vrcp2(vadd2(e, ONE2));
    return vfma2(C2(-2.0f), r, ONE2);
}

__global__ void zero_out_kernel(float* __restrict__ out, int n4) {
    int i = blockIdx.x * blockDim.x + threadIdx.x;
    if (i < n4) reinterpret_cast<float4*>(out)[i] = make_float4(0.f, 0.f, 0.f, 0.f);
}

__global__ void __launch_bounds__(128, 3)
domino_kernel(const float* __restrict__ x,
              const float* __restrict__ freqs,
              const float* __restrict__ W1, const float* __restrict__ b1,
              const float* __restrict__ W2, const float* __restrict__ b2,
              const float* __restrict__ W3, const float* __restrict__ b3,
              float* __restrict__ out)
{
    __shared__ __align__(16) float sm[SM_TOT];

    // stage weights/biases/freqs into shared (broadcast source for the block)
    for (int i = threadIdx.x; i < 2112; i += blockDim.x) sm[OFF_W1 + i] = W1[i];
    for (int i = threadIdx.x; i < 64;   i += blockDim.x) sm[OFF_B1 + i] = b1[i];
    for (int i = threadIdx.x; i < 2048; i += blockDim.x) sm[OFF_W2 + i] = W2[i];
    for (int i = threadIdx.x; i < 32;   i += blockDim.x) sm[OFF_B2 + i] = b2[i];
    for (int i = threadIdx.x; i < 256;  i += blockDim.x) sm[OFF_W3 + i] = W3[i];
    for (int i = threadIdx.x; i < 8;    i += blockDim.x) sm[OFF_B3 + i] = b3[i];
    for (int i = threadIdx.x; i < 8;    i += blockDim.x) sm[OFF_FR + i] = (i < 5) ? freqs[i] : 0.0f;
    __syncthreads();

    const int t = blockIdx.x * blockDim.x + threadIdx.x;   // grid exact
    const int n = t / 5;                                   // output point index

    // items 2t and 2t+1 (same point): 6 consecutive floats, 8B aligned
    const float2* xv = reinterpret_cast<const float2*>(x + (size_t)t * 6);
    const float2 v0 = xv[0], v1 = xv[1], v2 = xv[2];
    const float xa0 = v0.x, xa1 = v0.y, xa2 = v1.x;
    const float xb0 = v1.y, xb1 = v2.x, xb2 = v2.y;
    const float ma = (fabsf(xa0) > 1e-6f) ? 1.0f : 0.0f;   // padded-neighbor masks
    const float mb = (fabsf(xb0) > 1e-6f) ? 1.0f : 0.0f;

    // double2 = 4 floats. Row sizes in double2: W1 row(64f)=16, W2 row(32f)=8, W3 row(8f)=2.
    const double2* W1v = reinterpret_cast<const double2*>(sm + OFF_W1);
    const u64*     b1v = reinterpret_cast<const u64*>(sm + OFF_B1);
    const double2* W2v = reinterpret_cast<const double2*>(sm + OFF_W2);
    const u64*     b2v = reinterpret_cast<const u64*>(sm + OFF_B2);
    const double2* W3v = reinterpret_cast<const double2*>(sm + OFF_W3);
    const u64*     b3v = reinterpret_cast<const u64*>(sm + OFF_B3);

    // ---- feature vectors, PRE-PACKED as broadcast pairs (66 u64 regs) ----
    u64 fpa[33], fpb[33];
    fpa[0] = pk2(xa0, xa0); fpa[1] = pk2(xa1, xa1); fpa[2] = pk2(xa2, xa2);
    fpb[0] = pk2(xb0, xb0); fpb[1] = pk2(xb1, xb1); fpb[2] = pk2(xb2, xb2);
    {
        const u64 cab[3] = {pk2(xa0, xb0), pk2(xa1, xb1), pk2(xa2, xb2)};
#pragma unroll
        for (int m = 0; m < 5; m++) {
            const u64 frm2 = C2(sm[OFF_FR + m]);
#pragma unroll
            for (int d = 0; d < 3; d++) {
                float ta_, tb_;
                up2(vmul2(cab[d], frm2), ta_, tb_);   // one packed mul for both args
                float s, c;
                __sincosf(ta_, &s, &c);
                fpa[3  + m * 3 + d] = pk2(s, s);
                fpa[18 + m * 3 + d] = pk2(c, c);
                __sincosf(tb_, &s, &c);
                fpb[3  + m * 3 + d] = pk2(s, s);
                fpb[18 + m * 3 + d] = pk2(c, c);
            }
        }
    }

    // ---- layer 2 accumulators (32 outputs = 16 packed) per item ----
    u64 a2a[16], a2b[16];
#pragma unroll
    for (int kp = 0; kp < 16; kp++) { a2a[kp] = b2v[kp]; a2b[kp] = a2a[kp]; }

    // ---- layer 1 in 4 chunks of 16 outputs, streamed into layer 2 ----
#pragma unroll 1
    for (int jc = 0; jc < 4; jc++) {
        u64 c1a[8], c1b[8];
#pragma unroll
        for (int q = 0; q < 8; q++) { c1a[q] = b1v[jc * 8 + q]; c1b[q] = c1a[q]; }

#pragma unroll
        for (int i = 0; i < 33; i++) {
            const u64 ffa = fpa[i];
            const u64 ffb = fpb[i];
            const double2* wrow = W1v + i * 16 + jc * 4;
#pragma unroll
            for (int q = 0; q < 4; q++) {
                const double2 w = wrow[q];           // one LDS.128, serves both items
                const u64 wx = __double_as_longlong(w.x);
                const u64 wy = __double_as_longlong(w.y);
                fma2(c1a[2 * q],     ffa, wx);
                fma2(c1a[2 * q + 1], ffa, wy);
                fma2(c1b[2 * q],     ffb, wx);
                fma2(c1b[2 * q + 1], ffb, wy);
            }
        }

        // vector gelu the 16 chunk outputs of each item; stream into layer 2
#pragma unroll
        for (int q = 0; q < 8; q++) {
            float gau, gav, gbu, gbv;
            up2(gelu2(c1a[q]), gau, gav);
            up2(gelu2(c1b[q]), gbu, gbv);
            const u64 hau = pk2(gau, gau);
            const u64 hav = pk2(gav, gav);
            const u64 hbu = pk2(gbu, gbu);
            const u64 hbv = pk2(gbv, gbv);
            const int j0 = jc * 16 + 2 * q;
            const double2* w2a = W2v + (size_t)j0 * 8;   // row j0 (8 double2 = 32 floats)
            const double2* w2b = w2a + 8;                // row j0+1
#pragma unroll
            for (int kq = 0; kq < 8; kq++) {
                const double2 wa = w2a[kq];              // one LDS.128 serves both items
                const u64 wax = __double_as_longlong(wa.x);
                const u64 way = __double_as_longlong(wa.y);
                fma2(a2a[2 * kq],     hau, wax);
                fma2(a2a[2 * kq + 1], hau, way);
                fma2(a2b[2 * kq],     hbu, wax);
                fma2(a2b[2 * kq + 1], hbu, way);
                const double2 wb = w2b[kq];
                const u64 wbx = __double_as_longlong(wb.x);
                const u64 wby = __double_as_longlong(wb.y);
                fma2(a2a[2 * kq],     hav, wbx);
                fma2(a2a[2 * kq + 1], hav, wby);
                fma2(a2b[2 * kq],     hbv, wbx);
                fma2(a2b[2 * kq + 1], hbv, wby);
            }
        }
    }

    // ---- layer 3: consume a2 pairwise; h2 never materialized ----
    u64 a3a[4], a3b[4];
#pragma unroll
    for (int cp = 0; cp < 4; cp++) { a3a[cp] = b3v[cp]; a3b[cp] = a3a[cp]; }
#pragma unroll
    for (int q = 0; q < 16; q++) {
        float gau, gav, gbu, gbv;
        up2(gelu2(a2a[q]), gau, gav);
        up2(gelu2(a2b[q]), gbu, gbv);
        const u64 hau = pk2(gau, gau);
        const u64 hav = pk2(gav, gav);
        const u64 hbu = pk2(gbu, gbu);
        const u64 hbv = pk2(gbv, gbv);
        const int k0 = 2 * q;
        const double2* w3a = W3v + (size_t)k0 * 2;   // row k0 (2 double2 = 8 floats)
        const double2* w3b = w3a + 2;                // row k0+1
#pragma unroll
        for (int cq = 0; cq < 2; cq++) {
            const double2 wa = w3a[cq];
            const double2 wb = w3b[cq];
            const u64 wax = __double_as_longlong(wa.x);
            const u64 way = __double_as_longlong(wa.y);
            const u64 wbx = __double_as_longlong(wb.x);
            const u64 wby = __double_as_longlong(wb.y);
            fma2(a3a[2 * cq],     hau, wax);
            fma2(a3a[2 * cq + 1], hau, way);
            fma2(a3a[2 * cq],     hav, wbx);
            fma2(a3a[2 * cq + 1], hav, wby);
            fma2(a3b[2 * cq],     hbu, wax);
            fma2(a3b[2 * cq + 1], hbu, way);
            fma2(a3b[2 * cq],     hbv, wbx);
            fma2(a3b[2 * cq + 1], hbv, wby);
        }
    }

    // ---- vector tanh, mask-combine the two items, reduce via global RED ----
    const u64 ma2 = pk2(ma, ma);
    const u64 mb2 = pk2(mb, mb);
#pragma unroll
    for (int cp = 0; cp < 4; cp++) {
        const u64 ta = tanh2(a3a[cp]);
        const u64 tb = tanh2(a3b[cp]);
        u64 r = vmul2(ma2, ta);
        r = vfma2(mb2, tb, r);
        float r0, r1;
        up2(r, r0, r1);
        atomicAdd(&out[(size_t)(2 * cp)     * N_PTS + n], r0);
        atomicAdd(&out[(size_t)(2 * cp + 1) * N_PTS + n], r1);
    }
}

extern "C" void kernel_launch(void* const* d_in, const int* in_sizes, int n_in,
                              void* d_out, int out_size)
{
    (void)in_sizes; (void)n_in; (void)out_size;
    const float* x     = (const float*)d_in[0];
    // d_in[1] = grid : unused by the reference math
    const float* freqs = (const float*)d_in[2];
    const float* W1    = (const float*)d_in[3];
    const float* b1    = (const float*)d_in[4];
    const float* W2    = (const float*)d_in[5];
    const float* b2    = (const float*)d_in[6];
    const float* W3    = (const float*)d_in[7];
    const float* b3    = (const float*)d_in[8];
    float* out = (float*)d_out;

    // zero the output (8 * N_PTS floats = 786432 -> 196608 float4)
    const int n4 = (8 * N_PTS) / 4;
    zero_out_kernel<<<(n4 + 255) / 256, 256>>>(out, n4);

    domino_kernel<<<NTHRD / 128, 128>>>(x, freqs, W1, b1, W2, b2, W3, b3, out);
}

// round 14
// speedup vs baseline: 1.6599x; 1.0001x over previous
#include <cuda_runtime.h>
#include <math.h>

// DoMINO point-MLP, TWO (point,neighbor) items per thread (same point),
// weight LDS shared between items (3 CTAs/SM, no spill), f32x2 packed math;
// GELU via A&S 7.1.27 rational erf (1/sqrt2 folded); activations BATCHED
// ahead of each MAC streaming loop for independent MUFU chains (ILP).
// 33 -> 64 (gelu) -> 32 (gelu) -> 8 (tanh), masked sum over P=10,
// out (8,64,48,32) fp32, reduced via global RED into pre-zeroed d_out.

namespace {
constexpr int N_PTS = 98304;       // 64*48*32
constexpr int NB    = 10;
constexpr int NITEM = N_PTS * NB;  // 983040
constexpr int NTHRD = NITEM / 2;   // 491520 threads, 2 items each
// shared layout (floats); all offsets even -> 8B/16B aligned views OK
constexpr int OFF_W1 = 0;      // 33*64 = 2112
constexpr int OFF_B1 = 2112;   // 64
constexpr int OFF_W2 = 2176;   // 64*32 = 2048
constexpr int OFF_B2 = 4224;   // 32
constexpr int OFF_W3 = 4256;   // 32*8 = 256
constexpr int OFF_B3 = 4512;   // 8
constexpr int OFF_FR = 4520;   // 5 (+3 pad)
constexpr int SM_TOT = 4528;
}

typedef unsigned long long u64;

__device__ __forceinline__ u64 pk2(float x, float y) {
    u64 r;
    asm("mov.b64 %0, {%1, %2};" : "=l"(r) : "f"(x), "f"(y));
    return r;
}
__device__ __forceinline__ void up2(u64 a, float& x, float& y) {
    asm("mov.b64 {%0, %1}, %2;" : "=f"(x), "=f"(y) : "l"(a));
}
// packed dual fp32 FMA (accumulate form): d = a*b + d
__device__ __forceinline__ void fma2(u64& d, u64 a, u64 b) {
    asm("fma.rn.f32x2 %0, %1, %2, %0;" : "+l"(d) : "l"(a), "l"(b));
}
// packed dual fp32 FMA (3-operand): r = a*b + c
__device__ __forceinline__ u64 vfma2(u64 a, u64 b, u64 c) {
    u64 r;
    asm("fma.rn.f32x2 %0, %1, %2, %3;" : "=l"(r) : "l"(a), "l"(b), "l"(c));
    return r;
}
__device__ __forceinline__ u64 vmul2(u64 a, u64 b) {
    u64 r;
    asm("mul.rn.f32x2 %0, %1, %2;" : "=l"(r) : "l"(a), "l"(b));
    return r;
}
__device__ __forceinline__ u64 vadd2(u64 a, u64 b) {
    u64 r;
    asm("add.rn.f32x2 %0, %1, %2;" : "=l"(r) : "l"(a), "l"(b));
    return r;
}
__device__ __forceinline__ u64 C2(float c) { return pk2(c, c); }
// per-lane MUFU helpers on packed pairs
__device__ __forceinline__ u64 vrcp2(u64 a) {
    float x, y; up2(a, x, y);
    float rx, ry;
    asm("rcp.approx.f32 %0, %1;" : "=f"(rx) : "f"(x));
    asm("rcp.approx.f32 %0, %1;" : "=f"(ry) : "f"(y));
    return pk2(rx, ry);
}
__device__ __forceinline__ u64 vex2_2(u64 a) {
    float x, y; up2(a, x, y);
    float rx, ry;
    asm("ex2.approx.f32 %0, %1;" : "=f"(rx) : "f"(x));
    asm("ex2.approx.f32 %0, %1;" : "=f"(ry) : "f"(y));
    return pk2(rx, ry);
}

// Vector GELU, A&S 7.1.27 rational erf: erf(z) ~= 1 - 1/p(z)^4, |err|<=5e-4,
// with z = |v|/sqrt2 folded into the coefficients. One MUFU (rcp).
__device__ __forceinline__ u64 gelu2(u64 v) {
    const u64 ONE2 = C2(1.0f);
    const u64 sgn = v & 0x8000000080000000ULL;              // alu
    const u64 va  = v & 0x7FFFFFFF7FFFFFFFULL;              // alu
    u64 p  = vfma2(C2(0.019527000f), va, C2(0.00034366f));  // c4*|v| + c3
    p = vfma2(p, va, C2(0.11519450f));                      // + c2
    p = vfma2(p, va, C2(0.19686071f));                      // + c1
    p = vfma2(p, va, ONE2);                                 // p >= 1
    u64 p2 = vmul2(p, p);
    u64 p4 = vmul2(p2, p2);
    u64 r  = vrcp2(p4);                                     // 1/p^4
    u64 erfh = vfma2(C2(-0.5f), r, C2(0.5f));               // 0.5*erf(|z|) >= 0
    erfh |= sgn;                                            // alu: exact +/-
    return vmul2(v, vadd2(erfh, C2(0.5f)));
}
// Vector tanh on a packed pair: 1 - 2/(exp(2x)+1); saturates correctly at +/-inf.
__device__ __forceinline__ u64 tanh2(u64 v) {
    const u64 ONE2 = C2(1.0f);
    u64 e = vex2_2(vmul2(v, C2(2.8853900817779268f)));      // exp(2x) = 2^(2x*log2e)
    u64 r = vrcp2(vadd2(e, ONE2));
    return vfma2(C2(-2.0f), r, ONE2);
}

__global__ void zero_out_kernel(float* __restrict__ out, int n4) {
    int i = blockIdx.x * blockDim.x + threadIdx.x;
    if (i < n4) reinterpret_cast<float4*>(out)[i] = make_float4(0.f, 0.f, 0.f, 0.f);
}

__global__ void __launch_bounds__(128, 3)
domino_kernel(const float* __restrict__ x,
              const float* __restrict__ freqs,
              const float* __restrict__ W1, const float* __restrict__ b1,
              const float* __restrict__ W2, const float* __restrict__ b2,
              const float* __restrict__ W3, const float* __restrict__ b3,
              float* __restrict__ out)
{
    __shared__ __align__(16) float sm[SM_TOT];

    // stage weights/biases/freqs into shared (broadcast source for the block)
    for (int i = threadIdx.x; i < 2112; i += blockDim.x) sm[OFF_W1 + i] = W1[i];
    for (int i = threadIdx.x; i < 64;   i += blockDim.x) sm[OFF_B1 + i] = b1[i];
    for (int i = threadIdx.x; i < 2048; i += blockDim.x) sm[OFF_W2 + i] = W2[i];
    for (int i = threadIdx.x; i < 32;   i += blockDim.x) sm[OFF_B2 + i] = b2[i];
    for (int i = threadIdx.x; i < 256;  i += blockDim.x) sm[OFF_W3 + i] = W3[i];
    for (int i = threadIdx.x; i < 8;    i += blockDim.x) sm[OFF_B3 + i] = b3[i];
    for (int i = threadIdx.x; i < 8;    i += blockDim.x) sm[OFF_FR + i] = (i < 5) ? freqs[i] : 0.0f;
    __syncthreads();

    const int t = blockIdx.x * blockDim.x + threadIdx.x;   // grid exact
    const int n = t / 5;                                   // output point index

    // items 2t and 2t+1 (same point): 6 consecutive floats, 8B aligned
    const float2* xv = reinterpret_cast<const float2*>(x + (size_t)t * 6);
    const float2 v0 = xv[0], v1 = xv[1], v2 = xv[2];
    const float xa0 = v0.x, xa1 = v0.y, xa2 = v1.x;
    const float xb0 = v1.y, xb1 = v2.x, xb2 = v2.y;
    const float ma = (fabsf(xa0) > 1e-6f) ? 1.0f : 0.0f;   // padded-neighbor masks
    const float mb = (fabsf(xb0) > 1e-6f) ? 1.0f : 0.0f;

    // double2 = 4 floats. Row sizes in double2: W1 row(64f)=16, W2 row(32f)=8, W3 row(8f)=2.
    const double2* W1v = reinterpret_cast<const double2*>(sm + OFF_W1);
    const u64*     b1v = reinterpret_cast<const u64*>(sm + OFF_B1);
    const double2* W2v = reinterpret_cast<const double2*>(sm + OFF_W2);
    const u64*     b2v = reinterpret_cast<const u64*>(sm + OFF_B2);
    const double2* W3v = reinterpret_cast<const double2*>(sm + OFF_W3);
    const u64*     b3v = reinterpret_cast<const u64*>(sm + OFF_B3);

    // ---- feature vectors, PRE-PACKED as broadcast pairs ----
    u64 fpa[33], fpb[33];
    fpa[0] = pk2(xa0, xa0); fpa[1] = pk2(xa1, xa1); fpa[2] = pk2(xa2, xa2);
    fpb[0] = pk2(xb0, xb0); fpb[1] = pk2(xb1, xb1); fpb[2] = pk2(xb2, xb2);
    {
        const u64 cab[3] = {pk2(xa0, xb0), pk2(xa1, xb1), pk2(xa2, xb2)};
#pragma unroll
        for (int m = 0; m < 5; m++) {
            const u64 frm2 = C2(sm[OFF_FR + m]);
#pragma unroll
            for (int d = 0; d < 3; d++) {
                float ta_, tb_;
                up2(vmul2(cab[d], frm2), ta_, tb_);   // one packed mul for both args
                float s, c;
                __sincosf(ta_, &s, &c);
                fpa[3  + m * 3 + d] = pk2(s, s);
                fpa[18 + m * 3 + d] = pk2(c, c);
                __sincosf(tb_, &s, &c);
                fpb[3  + m * 3 + d] = pk2(s, s);
                fpb[18 + m * 3 + d] = pk2(c, c);
            }
        }
    }

    // ---- layer 2 accumulators (32 outputs = 16 packed) per item ----
    u64 a2a[16], a2b[16];
#pragma unroll
    for (int kp = 0; kp < 16; kp++) { a2a[kp] = b2v[kp]; a2b[kp] = a2a[kp]; }

    // ---- layer 1 in 4 chunks of 16 outputs, streamed into layer 2 ----
#pragma unroll 1
    for (int jc = 0; jc < 4; jc++) {
        u64 c1a[8], c1b[8];
#pragma unroll
        for (int q = 0; q < 8; q++) { c1a[q] = b1v[jc * 8 + q]; c1b[q] = c1a[q]; }

#pragma unroll
        for (int i = 0; i < 33; i++) {
            const u64 ffa = fpa[i];
            const u64 ffb = fpb[i];
            const double2* wrow = W1v + i * 16 + jc * 4;
#pragma unroll
            for (int q = 0; q < 4; q++) {
                const double2 w = wrow[q];           // one LDS.128, serves both items
                const u64 wx = __double_as_longlong(w.x);
                const u64 wy = __double_as_longlong(w.y);
                fma2(c1a[2 * q],     ffa, wx);
                fma2(c1a[2 * q + 1], ffa, wy);
                fma2(c1b[2 * q],     ffb, wx);
                fma2(c1b[2 * q + 1], ffb, wy);
            }
        }

        // BATCH: gelu all 16 chunk pairs first (independent MUFU chains)
#pragma unroll
        for (int q = 0; q < 8; q++) {
            c1a[q] = gelu2(c1a[q]);
            c1b[q] = gelu2(c1b[q]);
        }

        // stream the activated chunk into layer 2
#pragma unroll
        for (int q = 0; q < 8; q++) {
            float gau, gav, gbu, gbv;
            up2(c1a[q], gau, gav);
            up2(c1b[q], gbu, gbv);
            const u64 hau = pk2(gau, gau);
            const u64 hav = pk2(gav, gav);
            const u64 hbu = pk2(gbu, gbu);
            const u64 hbv = pk2(gbv, gbv);
            const int j0 = jc * 16 + 2 * q;
            const double2* w2a = W2v + (size_t)j0 * 8;   // row j0 (8 double2 = 32 floats)
            const double2* w2b = w2a + 8;                // row j0+1
#pragma unroll
            for (int kq = 0; kq < 8; kq++) {
                const double2 wa = w2a[kq];              // one LDS.128 serves both items
                const u64 wax = __double_as_longlong(wa.x);
                const u64 way = __double_as_longlong(wa.y);
                fma2(a2a[2 * kq],     hau, wax);
                fma2(a2a[2 * kq + 1], hau, way);
                fma2(a2b[2 * kq],     hbu, wax);
                fma2(a2b[2 * kq + 1], hbu, way);
                const double2 wb = w2b[kq];
                const u64 wbx = __double_as_longlong(wb.x);
                const u64 wby = __double_as_longlong(wb.y);
                fma2(a2a[2 * kq],     hav, wbx);
                fma2(a2a[2 * kq + 1], hav, wby);
                fma2(a2b[2 * kq],     hbv, wbx);
                fma2(a2b[2 * kq + 1], hbv, wby);
            }
        }
    }

    // ---- layer 3: BATCH all 32 gelus in place, then stream MACs ----
#pragma unroll
    for (int q = 0; q < 16; q++) {
        a2a[q] = gelu2(a2a[q]);
        a2b[q] = gelu2(a2b[q]);
    }

    u64 a3a[4], a3b[4];
#pragma unroll
    for (int cp = 0; cp < 4; cp++) { a3a[cp] = b3v[cp]; a3b[cp] = a3a[cp]; }
#pragma unroll
    for (int q = 0; q < 16; q++) {
        float gau, gav, gbu, gbv;
        up2(a2a[q], gau, gav);
        up2(a2b[q], gbu, gbv);
        const u64 hau = pk2(gau, gau);
        const u64 hav = pk2(gav, gav);
        const u64 hbu = pk2(gbu, gbu);
        const u64 hbv = pk2(gbv, gbv);
        const int k0 = 2 * q;
        const double2* w3a = W3v + (size_t)k0 * 2;   // row k0 (2 double2 = 8 floats)
        const double2* w3b = w3a + 2;                // row k0+1
#pragma unroll
        for (int cq = 0; cq < 2; cq++) {
            const double2 wa = w3a[cq];
            const double2 wb = w3b[cq];
            const u64 wax = __double_as_longlong(wa.x);
            const u64 way = __double_as_longlong(wa.y);
            const u64 wbx = __double_as_longlong(wb.x);
            const u64 wby = __double_as_longlong(wb.y);
            fma2(a3a[2 * cq],     hau, wax);
            fma2(a3a[2 * cq + 1], hau, way);
            fma2(a3a[2 * cq],     hav, wbx);
            fma2(a3a[2 * cq + 1], hav, wby);
            fma2(a3b[2 * cq],     hbu, wax);
            fma2(a3b[2 * cq + 1], hbu, way);
            fma2(a3b[2 * cq],     hbv, wbx);
            fma2(a3b[2 * cq + 1], hbv, wby);
        }
    }

    // ---- vector tanh, mask-combine the two items, reduce via global RED ----
    const u64 ma2 = pk2(ma, ma);
    const u64 mb2 = pk2(mb, mb);
#pragma unroll
    for (int cp = 0; cp < 4; cp++) {
        const u64 ta = tanh2(a3a[cp]);
        const u64 tb = tanh2(a3b[cp]);
        u64 r = vmul2(ma2, ta);
        r = vfma2(mb2, tb, r);
        float r0, r1;
        up2(r, r0, r1);
        atomicAdd(&out[(size_t)(2 * cp)     * N_PTS + n], r0);
        atomicAdd(&out[(size_t)(2 * cp + 1) * N_PTS + n], r1);
    }
}

extern "C" void kernel_launch(void* const* d_in, const int* in_sizes, int n_in,
                              void* d_out, int out_size)
{
    (void)in_sizes; (void)n_in; (void)out_size;
    const float* x     = (const float*)d_in[0];
    // d_in[1] = grid : unused by the reference math
    const float* freqs = (const float*)d_in[2];
    const float* W1    = (const float*)d_in[3];
    const float* b1    = (const float*)d_in[4];
    const float* W2    = (const float*)d_in[5];
    const float* b2    = (const float*)d_in[6];
    const float* W3    = (const float*)d_in[7];
    const float* b3    = (const float*)d_in[8];
    float* out = (float*)d_out;

    // zero the output (8 * N_PTS floats = 786432 -> 196608 float4)
    const int n4 = (8 * N_PTS) / 4;
    zero_out_kernel<<<(n4 + 255) / 256, 256>>>(out, n4);

    domino_kernel<<<NTHRD / 128, 128>>>(x, freqs, W1, b1, W2, b2, W3, b3, out);
}

// round 15
// speedup vs baseline: 1.9389x; 1.1681x over previous
#include <cuda_runtime.h>
#include <math.h>

// DoMINO point-MLP, TWO (point,neighbor) items per thread (same point),
// weight LDS shared between items (3 CTAs/SM, no spill), f32x2 packed math;
// GELU via tanh-form with HARDWARE MUFU.TANH (5 fma-ops + 2 MUFU per pair);
// final tanh is a bare MUFU.TANH.
// 33 -> 64 (gelu) -> 32 (gelu) -> 8 (tanh), masked sum over P=10,
// out (8,64,48,32) fp32, reduced via global RED into pre-zeroed d_out.

namespace {
constexpr int N_PTS = 98304;       // 64*48*32
constexpr int NB    = 10;
constexpr int NITEM = N_PTS * NB;  // 983040
constexpr int NTHRD = NITEM / 2;   // 491520 threads, 2 items each
// shared layout (floats); all offsets even -> 8B/16B aligned views OK
constexpr int OFF_W1 = 0;      // 33*64 = 2112
constexpr int OFF_B1 = 2112;   // 64
constexpr int OFF_W2 = 2176;   // 64*32 = 2048
constexpr int OFF_B2 = 4224;   // 32
constexpr int OFF_W3 = 4256;   // 32*8 = 256
constexpr int OFF_B3 = 4512;   // 8
constexpr int OFF_FR = 4520;   // 5 (+3 pad)
constexpr int SM_TOT = 4528;
}

typedef unsigned long long u64;

__device__ __forceinline__ u64 pk2(float x, float y) {
    u64 r;
    asm("mov.b64 %0, {%1, %2};" : "=l"(r) : "f"(x), "f"(y));
    return r;
}
__device__ __forceinline__ void up2(u64 a, float& x, float& y) {
    asm("mov.b64 {%0, %1}, %2;" : "=f"(x), "=f"(y) : "l"(a));
}
// packed dual fp32 FMA (accumulate form): d = a*b + d
__device__ __forceinline__ void fma2(u64& d, u64 a, u64 b) {
    asm("fma.rn.f32x2 %0, %1, %2, %0;" : "+l"(d) : "l"(a), "l"(b));
}
// packed dual fp32 FMA (3-operand): r = a*b + c
__device__ __forceinline__ u64 vfma2(u64 a, u64 b, u64 c) {
    u64 r;
    asm("fma.rn.f32x2 %0, %1, %2, %3;" : "=l"(r) : "l"(a), "l"(b), "l"(c));
    return r;
}
__device__ __forceinline__ u64 vmul2(u64 a, u64 b) {
    u64 r;
    asm("mul.rn.f32x2 %0, %1, %2;" : "=l"(r) : "l"(a), "l"(b));
    return r;
}
__device__ __forceinline__ u64 vadd2(u64 a, u64 b) {
    u64 r;
    asm("add.rn.f32x2 %0, %1, %2;" : "=l"(r) : "l"(a), "l"(b));
    return r;
}
__device__ __forceinline__ u64 C2(float c) { return pk2(c, c); }
// hardware tanh (MUFU.TANH) on both halves of a packed pair
__device__ __forceinline__ u64 vtanh2(u64 a) {
    float x, y; up2(a, x, y);
    float rx, ry;
    asm("tanh.approx.f32 %0, %1;" : "=f"(rx) : "f"(x));
    asm("tanh.approx.f32 %0, %1;" : "=f"(ry) : "f"(y));
    return pk2(rx, ry);
}

// Vector GELU, tanh form with hardware MUFU.TANH:
// gelu(v) = 0.5*v*(1 + tanh(0.7978845608*(v + 0.044715*v^3)))
// 5 fma-class f32x2 + 2 MUFU.TANH; no sign/abs ALU ops.
__device__ __forceinline__ u64 gelu2(u64 v) {
    u64 v2 = vmul2(v, v);
    u64 t  = vfma2(C2(0.0356774081f), v2, C2(0.7978845608f)); // 0.7979 + 0.035677*v^2
    u64 u  = vmul2(v, t);                                     // arg
    u64 th = vtanh2(u);
    u64 hv = vmul2(v, C2(0.5f));
    return vfma2(hv, th, hv);                                 // 0.5v + 0.5v*th
}

__global__ void zero_out_kernel(float* __restrict__ out, int n4) {
    int i = blockIdx.x * blockDim.x + threadIdx.x;
    if (i < n4) reinterpret_cast<float4*>(out)[i] = make_float4(0.f, 0.f, 0.f, 0.f);
}

__global__ void __launch_bounds__(128, 3)
domino_kernel(const float* __restrict__ x,
              const float* __restrict__ freqs,
              const float* __restrict__ W1, const float* __restrict__ b1,
              const float* __restrict__ W2, const float* __restrict__ b2,
              const float* __restrict__ W3, const float* __restrict__ b3,
              float* __restrict__ out)
{
    __shared__ __align__(16) float sm[SM_TOT];

    // stage weights/biases/freqs into shared (broadcast source for the block)
    for (int i = threadIdx.x; i < 2112; i += blockDim.x) sm[OFF_W1 + i] = W1[i];
    for (int i = threadIdx.x; i < 64;   i += blockDim.x) sm[OFF_B1 + i] = b1[i];
    for (int i = threadIdx.x; i < 2048; i += blockDim.x) sm[OFF_W2 + i] = W2[i];
    for (int i = threadIdx.x; i < 32;   i += blockDim.x) sm[OFF_B2 + i] = b2[i];
    for (int i = threadIdx.x; i < 256;  i += blockDim.x) sm[OFF_W3 + i] = W3[i];
    for (int i = threadIdx.x; i < 8;    i += blockDim.x) sm[OFF_B3 + i] = b3[i];
    for (int i = threadIdx.x; i < 8;    i += blockDim.x) sm[OFF_FR + i] = (i < 5) ? freqs[i] : 0.0f;
    __syncthreads();

    const int t = blockIdx.x * blockDim.x + threadIdx.x;   // grid exact
    const int n = t / 5;                                   // output point index

    // items 2t and 2t+1 (same point): 6 consecutive floats, 8B aligned
    const float2* xv = reinterpret_cast<const float2*>(x + (size_t)t * 6);
    const float2 v0 = xv[0], v1 = xv[1], v2 = xv[2];
    const float xa0 = v0.x, xa1 = v0.y, xa2 = v1.x;
    const float xb0 = v1.y, xb1 = v2.x, xb2 = v2.y;
    const float ma = (fabsf(xa0) > 1e-6f) ? 1.0f : 0.0f;   // padded-neighbor masks
    const float mb = (fabsf(xb0) > 1e-6f) ? 1.0f : 0.0f;

    // double2 = 4 floats. Row sizes in double2: W1 row(64f)=16, W2 row(32f)=8, W3 row(8f)=2.
    const double2* W1v = reinterpret_cast<const double2*>(sm + OFF_W1);
    const u64*     b1v = reinterpret_cast<const u64*>(sm + OFF_B1);
    const double2* W2v = reinterpret_cast<const double2*>(sm + OFF_W2);
    const u64*     b2v = reinterpret_cast<const u64*>(sm + OFF_B2);
    const double2* W3v = reinterpret_cast<const double2*>(sm + OFF_W3);
    const u64*     b3v = reinterpret_cast<const u64*>(sm + OFF_B3);

    // ---- feature vectors, PRE-PACKED as broadcast pairs ----
    u64 fpa[33], fpb[33];
    fpa[0] = pk2(xa0, xa0); fpa[1] = pk2(xa1, xa1); fpa[2] = pk2(xa2, xa2);
    fpb[0] = pk2(xb0, xb0); fpb[1] = pk2(xb1, xb1); fpb[2] = pk2(xb2, xb2);
    {
        const u64 cab[3] = {pk2(xa0, xb0), pk2(xa1, xb1), pk2(xa2, xb2)};
#pragma unroll
        for (int m = 0; m < 5; m++) {
            const u64 frm2 = C2(sm[OFF_FR + m]);
#pragma unroll
            for (int d = 0; d < 3; d++) {
                float ta_, tb_;
                up2(vmul2(cab[d], frm2), ta_, tb_);   // one packed mul for both args
                float s, c;
                __sincosf(ta_, &s, &c);
                fpa[3  + m * 3 + d] = pk2(s, s);
                fpa[18 + m * 3 + d] = pk2(c, c);
                __sincosf(tb_, &s, &c);
                fpb[3  + m * 3 + d] = pk2(s, s);
                fpb[18 + m * 3 + d] = pk2(c, c);
            }
        }
    }

    // ---- layer 2 accumulators (32 outputs = 16 packed) per item ----
    u64 a2a[16], a2b[16];
#pragma unroll
    for (int kp = 0; kp < 16; kp++) { a2a[kp] = b2v[kp]; a2b[kp] = a2a[kp]; }

    // ---- layer 1 in 4 chunks of 16 outputs, streamed into layer 2 ----
#pragma unroll 1
    for (int jc = 0; jc < 4; jc++) {
        u64 c1a[8], c1b[8];
#pragma unroll
        for (int q = 0; q < 8; q++) { c1a[q] = b1v[jc * 8 + q]; c1b[q] = c1a[q]; }

#pragma unroll
        for (int i = 0; i < 33; i++) {
            const u64 ffa = fpa[i];
            const u64 ffb = fpb[i];
            const double2* wrow = W1v + i * 16 + jc * 4;
#pragma unroll
            for (int q = 0; q < 4; q++) {
                const double2 w = wrow[q];           // one LDS.128, serves both items
                const u64 wx = __double_as_longlong(w.x);
                const u64 wy = __double_as_longlong(w.y);
                fma2(c1a[2 * q],     ffa, wx);
                fma2(c1a[2 * q + 1], ffa, wy);
                fma2(c1b[2 * q],     ffb, wx);
                fma2(c1b[2 * q + 1], ffb, wy);
            }
        }

        // gelu all 16 chunk pairs (independent MUFU.TANH chains)
#pragma unroll
        for (int q = 0; q < 8; q++) {
            c1a[q] = gelu2(c1a[q]);
            c1b[q] = gelu2(c1b[q]);
        }

        // stream the activated chunk into layer 2
#pragma unroll
        for (int q = 0; q < 8; q++) {
            float gau, gav, gbu, gbv;
            up2(c1a[q], gau, gav);
            up2(c1b[q], gbu, gbv);
            const u64 hau = pk2(gau, gau);
            const u64 hav = pk2(gav, gav);
            const u64 hbu = pk2(gbu, gbu);
            const u64 hbv = pk2(gbv, gbv);
            const int j0 = jc * 16 + 2 * q;
            const double2* w2a = W2v + (size_t)j0 * 8;   // row j0 (8 double2 = 32 floats)
            const double2* w2b = w2a + 8;                // row j0+1
#pragma unroll
            for (int kq = 0; kq < 8; kq++) {
                const double2 wa = w2a[kq];              // one LDS.128 serves both items
                const u64 wax = __double_as_longlong(wa.x);
                const u64 way = __double_as_longlong(wa.y);
                fma2(a2a[2 * kq],     hau, wax);
                fma2(a2a[2 * kq + 1], hau, way);
                fma2(a2b[2 * kq],     hbu, wax);
                fma2(a2b[2 * kq + 1], hbu, way);
                const double2 wb = w2b[kq];
                const u64 wbx = __double_as_longlong(wb.x);
                const u64 wby = __double_as_longlong(wb.y);
                fma2(a2a[2 * kq],     hav, wbx);
                fma2(a2a[2 * kq + 1], hav, wby);
                fma2(a2b[2 * kq],     hbv, wbx);
                fma2(a2b[2 * kq + 1], hbv, wby);
            }
        }
    }

    // ---- layer 3: gelu all 32 pairs in place, then stream MACs ----
#pragma unroll
    for (int q = 0; q < 16; q++) {
        a2a[q] = gelu2(a2a[q]);
        a2b[q] = gelu2(a2b[q]);
    }

    u64 a3a[4], a3b[4];
#pragma unroll
    for (int cp = 0; cp < 4; cp++) { a3a[cp] = b3v[cp]; a3b[cp] = a3a[cp]; }
#pragma unroll
    for (int q = 0; q < 16; q++) {
        float gau, gav, gbu, gbv;
        up2(a2a[q], gau, gav);
        up2(a2b[q], gbu, gbv);
        const u64 hau = pk2(gau, gau);
        const u64 hav = pk2(gav, gav);
        const u64 hbu = pk2(gbu, gbu);
        const u64 hbv = pk2(gbv, gbv);
        const int k0 = 2 * q;
        const double2* w3a = W3v + (size_t)k0 * 2;   // row k0 (2 double2 = 8 floats)
        const double2* w3b = w3a + 2;                // row k0+1
#pragma unroll
        for (int cq = 0; cq < 2; cq++) {
            const double2 wa = w3a[cq];
            const double2 wb = w3b[cq];
            const u64 wax = __double_as_longlong(wa.x);
            const u64 way = __double_as_longlong(wa.y);
            const u64 wbx = __double_as_longlong(wb.x);
            const u64 wby = __double_as_longlong(wb.y);
            fma2(a3a[2 * cq],     hau, wax);
            fma2(a3a[2 * cq + 1], hau, way);
            fma2(a3a[2 * cq],     hav, wbx);
            fma2(a3a[2 * cq + 1], hav, wby);
            fma2(a3b[2 * cq],     hbu, wax);
            fma2(a3b[2 * cq + 1], hbu, way);
            fma2(a3b[2 * cq],     hbv, wbx);
            fma2(a3b[2 * cq + 1], hbv, wby);
        }
    }

    // ---- hardware tanh, mask-combine the two items, reduce via global RED ----
    const u64 ma2 = pk2(ma, ma);
    const u64 mb2 = pk2(mb, mb);
#pragma unroll
    for (int cp = 0; cp < 4; cp++) {
        const u64 ta = vtanh2(a3a[cp]);
        const u64 tb = vtanh2(a3b[cp]);
        u64 r = vmul2(ma2, ta);
        r = vfma2(mb2, tb, r);
        float r0, r1;
        up2(r, r0, r1);
        atomicAdd(&out[(size_t)(2 * cp)     * N_PTS + n], r0);
        atomicAdd(&out[(size_t)(2 * cp + 1) * N_PTS + n], r1);
    }
}

extern "C" void kernel_launch(void* const* d_in, const int* in_sizes, int n_in,
                              void* d_out, int out_size)
{
    (void)in_sizes; (void)n_in; (void)out_size;
    const float* x     = (const float*)d_in[0];
    // d_in[1] = grid : unused by the reference math
    const float* freqs = (const float*)d_in[2];
    const float* W1    = (const float*)d_in[3];
    const float* b1    = (const float*)d_in[4];
    const float* W2    = (const float*)d_in[5];
    const float* b2    = (const float*)d_in[6];
    const float* W3    = (const float*)d_in[7];
    const float* b3    = (const float*)d_in[8];
    float* out = (float*)d_out;

    // zero the output (8 * N_PTS floats = 786432 -> 196608 float4)
    const int n4 = (8 * N_PTS) / 4;
    zero_out_kernel<<<(n4 + 255) / 256, 256>>>(out, n4);

    domino_kernel<<<NTHRD / 128, 128>>>(x, freqs, W1, b1, W2, b2, W3, b3, out);
}